// round 8
// baseline (speedup 1.0000x reference)
#include <cuda_runtime.h>
#include <math.h>

#define NN 50000
#define EE 800000
#define CC 32
#define ZZ 10
#define LL 2
#define NB 8
#define HH 64
#define INV_AVG (1.0f/16.0f)
#define RCUT_INV (1.0f/5.0f)

typedef unsigned long long u64;

// ---------------- scratch (static device globals; no allocation) -------------
__device__ float4 g_sv [NN*CC];   // {s, v0, v1, v2}
__device__ float4 g_up [NN*CC];   // {su, vu0, vu1, vu2}
__device__ float4 g_acc[NN*CC];   // {S, V0, V1, V2}
__device__ float4 g_Y1 [EE];      // {y0, y1, y2, pad}
__device__ float  g_ef [EE*NB];
__device__ int2   g_edge[EE];     // {src, dst}
__device__ int    g_z  [NN];

// ---------------- packed fp32x2 helpers (SASS FFMA2 via PTX) -----------------
__device__ __forceinline__ u64 pack2(float lo, float hi) {
    u64 r; asm("mov.b64 %0, {%1,%2};" : "=l"(r) : "f"(lo), "f"(hi)); return r;
}
__device__ __forceinline__ float2 unpk(u64 v) {
    float2 f; asm("mov.b64 {%0,%1}, %2;" : "=f"(f.x), "=f"(f.y) : "l"(v)); return f;
}
__device__ __forceinline__ void ffma2(u64 &d, u64 a, u64 b) {
    asm("fma.rn.f32x2 %0, %1, %2, %0;" : "+l"(d) : "l"(a), "l"(b));
}
__device__ __forceinline__ float silu(float x) {
    return __fdividef(x, 1.0f + __expf(-x));
}
__device__ __forceinline__ void red_v4(float4* p, float a, float b, float c, float d) {
    asm volatile("red.global.add.v4.f32 [%0], {%1,%2,%3,%4};"
                 :: "l"(p), "f"(a), "f"(b), "f"(c), "f"(d) : "memory");
}

// ---------------- species index from one-hot ---------------------------------
__global__ void k_zidx(const float* __restrict__ attrs) {
    int n = blockIdx.x * blockDim.x + threadIdx.x;
    if (n >= NN) return;
    int z = 0;
#pragma unroll
    for (int j = 0; j < ZZ; j++)
        if (attrs[n*ZZ + j] > 0.5f) z = j;
    g_z[n] = z;
}

// ---------------- s = onehot @ W_embed, v = 0 --------------------------------
__global__ void k_embed(const float* __restrict__ W_embed) {
    int idx = blockIdx.x * blockDim.x + threadIdx.x;
    if (idx >= NN*CC) return;
    int n = idx >> 5, c = idx & 31;
    g_sv[idx] = make_float4(W_embed[g_z[n]*CC + c], 0.f, 0.f, 0.f);
}

// ---------------- edge geometry: Y1 + radial features + packed index ---------
// NOTE: precise sinf per basis fn — fast-math trig here fails the 1e-3 gate.
__global__ void k_geom(const float* __restrict__ pos,
                       const float* __restrict__ shifts,
                       const int* __restrict__ src,
                       const int* __restrict__ dst) {
    int e = blockIdx.x * blockDim.x + threadIdx.x;
    if (e >= EE) return;
    int si = src[e], di = dst[e];
    g_edge[e] = make_int2(si, di);
    float vx = pos[di*3+0] - pos[si*3+0] + shifts[e*3+0];
    float vy = pos[di*3+1] - pos[si*3+1] + shifts[e*3+1];
    float vz = pos[di*3+2] - pos[si*3+2] + shifts[e*3+2];
    float r  = sqrtf(vx*vx + vy*vy + vz*vz);
    float rs = fmaxf(r, 1e-9f);
    float inv = 1.0f / rs;
    g_Y1[e] = make_float4(vx*inv, vy*inv, vz*inv, 0.f);
    float x = r * RCUT_INV;
    float fc = 0.f;
    if (x < 1.0f) {
        float x2 = x*x, x3 = x2*x;
        float x6 = x3*x3, x7 = x6*x, x8 = x7*x;
        fc = 1.0f - 28.0f*x6 + 48.0f*x7 - 21.0f*x8;   // P=6 polynomial cutoff
    }
    float coef = 0.6324555320336759f * fc * inv;       // sqrt(2/RCUT)*fc/rs
    float arg0 = rs * (float)M_PI * RCUT_INV;
#pragma unroll
    for (int nb = 0; nb < NB; nb++)
        g_ef[e*NB + nb] = coef * sinf((float)(nb+1) * arg0);
}

// ---------------- node "up" linears: su = s@Wus, vu = v@Wuv (+zero acc) ------
#define NWU 16
__global__ void k_nodeup(const float* __restrict__ Wus,
                         const float* __restrict__ Wuv) {
    __shared__ float sWs[CC*CC], sWv[CC*CC];
    __shared__ float st[NWU][128];
    int tid = threadIdx.x;
    for (int i = tid; i < CC*CC; i += blockDim.x) { sWs[i] = Wus[i]; sWv[i] = Wuv[i]; }
    __syncthreads();
    int warp = tid >> 5, lane = tid & 31;
    int n = blockIdx.x * NWU + warp;
    if (n >= NN) return;
    float* xs = st[warp];
    float* xv = st[warp] + 32;
    float4 f = g_sv[n*CC + lane];
    g_acc[n*CC + lane] = make_float4(0.f, 0.f, 0.f, 0.f);   // zero accumulators here
    xs[lane]       = f.x;
    xv[lane*3 + 0] = f.y;
    xv[lane*3 + 1] = f.z;
    xv[lane*3 + 2] = f.w;
    __syncwarp();
    float a = 0.f, u0 = 0.f, u1 = 0.f, u2 = 0.f;
#pragma unroll
    for (int k = 0; k < CC; k++) {
        float ws = sWs[k*CC + lane], wv = sWv[k*CC + lane];
        a  += xs[k]     * ws;
        u0 += xv[k*3+0] * wv;
        u1 += xv[k*3+1] * wv;
        u2 += xv[k*3+2] * wv;
    }
    g_up[n*CC + lane] = make_float4(a, u0, u1, u2);
}

// ---------------- fused edge kernel ------------------------------------------
// Phase A (lane = edge): radial MLP stages 1-2 with broadcast LDS.128 weights
//   and FFMA2 packed math; silu'd hidden written transposed to per-warp smem;
//   (src,dst) staged to per-warp smem.
// Phase B (lane = channel): stage-3 [64 -> 5x32] register-blocked over TWO
//   16-edge halves (acc[40]) — R3T swept 2x/batch instead of 4x. Epilogue in
//   8-edge groups with batched uv/Y1 prefetch.
#define EW 6
#define ETPB (EW*32)
#define HWF 2048          // 64*32 floats per warp
#define KP 68             // padded k stride (272B, conflict-free, 16B-aligned)

__global__ void __launch_bounds__(ETPB, 2)
k_edge(const float* __restrict__ R1,
       const float* __restrict__ R2,
       const float* __restrict__ R3) {
    extern __shared__ float smf[];
    float* sR1  = smf;                      // 512
    float* sR2  = sR1 + NB*HH;              // 4096
    float* sR3T = sR2 + HH*HH;              // 5*32*68 = 10880
    float* hall = sR3T + 5*CC*KP;           // EW*2048
    int2*  sdall = (int2*)(hall + EW*HWF);  // EW*32 int2
    int tid = threadIdx.x;
    for (int i = tid; i < NB*HH;   i += ETPB) sR1[i] = R1[i];
    for (int i = tid; i < HH*HH;   i += ETPB) sR2[i] = R2[i];
    for (int i = tid; i < 5*CC*HH; i += ETPB) {
        int k = i & 63, rest = i >> 6;
        int c = rest & 31, p = rest >> 5;
        sR3T[p*(CC*KP) + c*KP + k] = R3[k*5*CC + p*CC + c];
    }
    __syncthreads();

    int warp = tid >> 5, lane = tid & 31;
    float* hw  = hall + warp*HWF;
    int2*  sdw = sdall + warp*32;
    const int nbatch = EE/32;   // 25000, exact

    for (int b = blockIdx.x*EW + warp; b < nbatch; b += gridDim.x*EW) {
        int ebase = b*32;
        int e = ebase + lane;

        // ======== phase A: lane = edge ========
        sdw[lane] = __ldg(g_edge + e);          // stage (src,dst) for phase B
        float4 efa = *(const float4*)&g_ef[e*NB];
        float4 efb = *(const float4*)&g_ef[e*NB + 4];
        float ef[8] = {efa.x, efa.y, efa.z, efa.w, efb.x, efb.y, efb.z, efb.w};

        // stage 1: [8] -> [64]
        u64 h2[32];
#pragma unroll
        for (int m = 0; m < 32; m++) h2[m] = 0ull;
#pragma unroll
        for (int k = 0; k < 8; k++) {
            u64 a = pack2(ef[k], ef[k]);
            const ulonglong2* row = (const ulonglong2*)(sR1 + k*HH);
#pragma unroll
            for (int m = 0; m < 16; m++) {
                ulonglong2 w = row[m];
                ffma2(h2[2*m],   a, w.x);
                ffma2(h2[2*m+1], a, w.y);
            }
        }
#pragma unroll
        for (int m = 0; m < 32; m++) {
            float2 f = unpk(h2[m]);
            h2[m] = pack2(silu(f.x), silu(f.y));
        }

        // stage 2: [64] -> [64], split into two output halves (reg pressure)
#pragma unroll
        for (int Hh = 0; Hh < 2; Hh++) {
            u64 acc[16];
#pragma unroll
            for (int m = 0; m < 16; m++) acc[m] = 0ull;
#pragma unroll 4
            for (int kk = 0; kk < 32; kk++) {
                float2 hk = unpk(h2[kk]);
                u64 a0 = pack2(hk.x, hk.x);
                u64 a1 = pack2(hk.y, hk.y);
                const ulonglong2* r0 = (const ulonglong2*)(sR2 + (2*kk)*HH   + Hh*32);
                const ulonglong2* r1 = (const ulonglong2*)(sR2 + (2*kk+1)*HH + Hh*32);
#pragma unroll
                for (int m = 0; m < 8; m++) {
                    ulonglong2 w0 = r0[m], w1 = r1[m];
                    ffma2(acc[2*m],   a0, w0.x);
                    ffma2(acc[2*m+1], a0, w0.y);
                    ffma2(acc[2*m],   a1, w1.x);
                    ffma2(acc[2*m+1], a1, w1.y);
                }
            }
#pragma unroll
            for (int m = 0; m < 16; m++) {
                float2 f = unpk(acc[m]);
                hw[(Hh*32 + 2*m)*32   + lane] = silu(f.x);
                hw[(Hh*32 + 2*m+1)*32 + lane] = silu(f.y);
            }
        }
        __syncwarp();

        // ======== phase B: lane = channel, 2 halves of 16 edges ========
#pragma unroll 1
        for (int half = 0; half < 2; half++) {
            const float* hq = hw + half*16;
            u64 acc[40];   // [p][pair0..7]
#pragma unroll
            for (int i = 0; i < 40; i++) acc[i] = 0ull;
            const float* r3base = sR3T + lane*KP;
#pragma unroll 2
            for (int k4 = 0; k4 < 16; k4++) {
                float4 w40 = *(const float4*)(r3base + 0*(CC*KP) + 4*k4);
                float4 w41 = *(const float4*)(r3base + 1*(CC*KP) + 4*k4);
                float4 w42 = *(const float4*)(r3base + 2*(CC*KP) + 4*k4);
                float4 w43 = *(const float4*)(r3base + 3*(CC*KP) + 4*k4);
                float4 w44 = *(const float4*)(r3base + 4*(CC*KP) + 4*k4);
                float wv0[4] = {w40.x, w40.y, w40.z, w40.w};
                float wv1[4] = {w41.x, w41.y, w41.z, w41.w};
                float wv2[4] = {w42.x, w42.y, w42.z, w42.w};
                float wv3[4] = {w43.x, w43.y, w43.z, w43.w};
                float wv4[4] = {w44.x, w44.y, w44.z, w44.w};
#pragma unroll
                for (int kk = 0; kk < 4; kk++) {
                    const float* hk = hq + (4*k4 + kk)*32;
                    ulonglong2 ha = *(const ulonglong2*)(hk);
                    ulonglong2 hb = *(const ulonglong2*)(hk + 4);
                    ulonglong2 hc = *(const ulonglong2*)(hk + 8);
                    ulonglong2 hd = *(const ulonglong2*)(hk + 12);
                    u64 hp[8] = {ha.x, ha.y, hb.x, hb.y, hc.x, hc.y, hd.x, hd.y};
                    u64 w2;
                    w2 = pack2(wv0[kk], wv0[kk]);
#pragma unroll
                    for (int pr = 0; pr < 8; pr++) ffma2(acc[0*8+pr], hp[pr], w2);
                    w2 = pack2(wv1[kk], wv1[kk]);
#pragma unroll
                    for (int pr = 0; pr < 8; pr++) ffma2(acc[1*8+pr], hp[pr], w2);
                    w2 = pack2(wv2[kk], wv2[kk]);
#pragma unroll
                    for (int pr = 0; pr < 8; pr++) ffma2(acc[2*8+pr], hp[pr], w2);
                    w2 = pack2(wv3[kk], wv3[kk]);
#pragma unroll
                    for (int pr = 0; pr < 8; pr++) ffma2(acc[3*8+pr], hp[pr], w2);
                    w2 = pack2(wv4[kk], wv4[kk]);
#pragma unroll
                    for (int pr = 0; pr < 8; pr++) ffma2(acc[4*8+pr], hp[pr], w2);
                }
            }

            // epilogue: 2 groups of 8 edges, batched prefetch then math
#pragma unroll 1
            for (int g = 0; g < 2; g++) {
                float4 uvr[8];
                float4 yr[8];
                int    dstr[8];
#pragma unroll
                for (int j = 0; j < 8; j++) {
                    int jw = half*16 + g*8 + j;       // index within batch
                    int2 sd = sdw[jw];                // broadcast LDS
                    dstr[j] = sd.y;
                    yr[j]   = __ldg(g_Y1 + ebase + jw);
                    uvr[j]  = __ldg(g_up + sd.x*CC + lane);
                }
#pragma unroll
                for (int j = 0; j < 8; j++) {
                    int jj = g*8 + j;                 // within half: 0..15
                    int pair = jj >> 1, hh = jj & 1;
                    float2 a0 = unpk(acc[0*8+pair]);
                    float2 a1 = unpk(acc[1*8+pair]);
                    float2 a2 = unpk(acc[2*8+pair]);
                    float2 a3 = unpk(acc[3*8+pair]);
                    float2 a4 = unpk(acc[4*8+pair]);
                    float w0 = hh ? a0.y : a0.x;
                    float w1 = hh ? a1.y : a1.x;
                    float w2v= hh ? a2.y : a2.x;
                    float w3 = hh ? a3.y : a3.x;
                    float w4 = hh ? a4.y : a4.x;
                    float y0 = yr[j].x, y1 = yr[j].y, y2 = yr[j].z;
                    float ss = uvr[j].x, v0 = uvr[j].y, v1 = uvr[j].z, v2 = uvr[j].w;
                    float dot = v0*y0 + v1*y1 + v2*y2;
                    float c0 = v1*y2 - v2*y1;
                    float c1 = v2*y0 - v0*y2;
                    float c2 = v0*y1 - v1*y0;
                    float ms = w0*ss + w3*dot;
                    float m0 = w1*ss*y0 + w2v*v0 + w4*c0;
                    float m1 = w1*ss*y1 + w2v*v1 + w4*c1;
                    float m2 = w1*ss*y2 + w2v*v2 + w4*c2;
                    red_v4(g_acc + dstr[j]*CC + lane, ms, m0, m1, m2);
                }
            }
        }
        __syncwarp();
    }
}

// ---------------- node update: out linears, skip, product block --------------
#define NWB 16
__global__ void k_nodeupd(const float* __restrict__ Wouts,
                          const float* __restrict__ Woutv,
                          const float* __restrict__ Wscs,
                          const float* __restrict__ Wscv,
                          const float* __restrict__ Wp,
                          const float* __restrict__ Wlins,
                          const float* __restrict__ Wlinv,
                          float* __restrict__ out, int l) {
    __shared__ float sWos[CC*CC], sWov[CC*CC], sWls[CC*CC], sWlv[CC*CC];
    __shared__ float st[NWB][256];
    int tid = threadIdx.x;
    for (int i = tid; i < CC*CC; i += blockDim.x) {
        sWos[i] = Wouts[i]; sWov[i] = Woutv[i];
        sWls[i] = Wlins[i]; sWlv[i] = Wlinv[i];
    }
    __syncthreads();
    int warp = tid >> 5, lane = tid & 31;
    int n = blockIdx.x * NWB + warp;
    if (n >= NN) return;

    float* xs = st[warp];
    float* xv = xs + 32;
    float* ys = xv + 96;
    float* yv = ys + 32;

    int z = g_z[n];
    float4 a4 = g_acc[n*CC + lane];
    float4 o4 = g_sv [n*CC + lane];
    xs[lane]       = a4.x * INV_AVG;
    xv[lane*3 + 0] = a4.y * INV_AVG;
    xv[lane*3 + 1] = a4.z * INV_AVG;
    xv[lane*3 + 2] = a4.w * INV_AVG;
    ys[lane]       = o4.x;
    yv[lane*3 + 0] = o4.y;
    yv[lane*3 + 1] = o4.z;
    yv[lane*3 + 2] = o4.w;
    __syncwarp();

    const float* Ws = Wscs + z*CC*CC;
    const float* Wv = Wscv + z*CC*CC;
    float s2 = 0.f, v20 = 0.f, v21 = 0.f, v22 = 0.f;
    float scs = 0.f, sv0 = 0.f, sv1 = 0.f, sv2 = 0.f;
#pragma unroll
    for (int k = 0; k < CC; k++) {
        float wo = sWos[k*CC + lane], wvv = sWov[k*CC + lane];
        s2  += xs[k]     * wo;
        v20 += xv[k*3+0] * wvv;
        v21 += xv[k*3+1] * wvv;
        v22 += xv[k*3+2] * wvv;
        float as = __ldg(Ws + k*CC + lane), av = __ldg(Wv + k*CC + lane);
        scs += ys[k]     * as;
        sv0 += yv[k*3+0] * av;
        sv1 += yv[k*3+1] * av;
        sv2 += yv[k*3+2] * av;
    }

    float we0 = __ldg(Wp + (z*5+0)*CC + lane);
    float we1 = __ldg(Wp + (z*5+1)*CC + lane);
    float we2 = __ldg(Wp + (z*5+2)*CC + lane);
    float we3 = __ldg(Wp + (z*5+3)*CC + lane);
    float we4 = __ldg(Wp + (z*5+4)*CC + lane);

    float vdot = v20*v20 + v21*v21 + v22*v22;
    float ps  = we0*s2 + we1*s2*s2 + we2*vdot;
    float pv0 = we3*v20 + we4*s2*v20;
    float pv1 = we3*v21 + we4*s2*v21;
    float pv2 = we3*v22 + we4*s2*v22;
    __syncwarp();
    xs[lane] = ps;
    xv[lane*3+0] = pv0; xv[lane*3+1] = pv1; xv[lane*3+2] = pv2;
    __syncwarp();

    float sn = scs, vn0 = sv0, vn1 = sv1, vn2 = sv2;
#pragma unroll
    for (int k = 0; k < CC; k++) {
        float wl = sWls[k*CC + lane], wlv = sWlv[k*CC + lane];
        sn  += xs[k]     * wl;
        vn0 += xv[k*3+0] * wlv;
        vn1 += xv[k*3+1] * wlv;
        vn2 += xv[k*3+2] * wlv;
    }
    g_sv[n*CC + lane] = make_float4(sn, vn0, vn1, vn2);
    out[n*(LL*CC) + l*CC + lane] = sn;
}

// ---------------- launch ------------------------------------------------------
extern "C" void kernel_launch(void* const* d_in, const int* in_sizes, int n_in,
                              void* d_out, int out_size) {
    const float* pos     = (const float*)d_in[0];
    const float* attrs   = (const float*)d_in[1];
    const float* shifts  = (const float*)d_in[2];
    const float* W_embed = (const float*)d_in[3];
    const float* W_up_s  = (const float*)d_in[4];
    const float* W_up_v  = (const float*)d_in[5];
    const float* R1      = (const float*)d_in[6];
    const float* R2      = (const float*)d_in[7];
    const float* R3      = (const float*)d_in[8];
    const float* W_out_s = (const float*)d_in[9];
    const float* W_out_v = (const float*)d_in[10];
    const float* Wsc_s   = (const float*)d_in[11];
    const float* Wsc_v   = (const float*)d_in[12];
    const float* Wp      = (const float*)d_in[13];
    const float* W_lin_s = (const float*)d_in[14];
    const float* W_lin_v = (const float*)d_in[15];
    const int*   ei      = (const int*)d_in[16];
    const int* src = ei;
    const int* dst = ei + EE;
    float* out = (float*)d_out;

    // floats: 15488 (weights) + EW*2048 (h) + EW*64 (int2 staging) = 28160
    int smem = (NB*HH + HH*HH + 5*CC*KP + EW*HWF + EW*64) * (int)sizeof(float); // 112640 B
    cudaFuncSetAttribute(k_edge, cudaFuncAttributeMaxDynamicSharedMemorySize, smem);

    k_zidx <<<(NN + 255)/256, 256>>>(attrs);
    k_embed<<<(NN*CC + 255)/256, 256>>>(W_embed);
    k_geom <<<(EE + 255)/256, 256>>>(pos, shifts, src, dst);

    for (int l = 0; l < LL; l++) {
        k_nodeup<<<(NN + NWU - 1)/NWU, NWU*32>>>(W_up_s + l*CC*CC, W_up_v + l*CC*CC);
        k_edge  <<<296, ETPB, smem>>>(R1 + l*NB*HH, R2 + l*HH*HH, R3 + l*HH*5*CC);
        k_nodeupd<<<(NN + NWB - 1)/NWB, NWB*32>>>(
            W_out_s + l*CC*CC, W_out_v + l*CC*CC,
            Wsc_s + l*ZZ*CC*CC, Wsc_v + l*ZZ*CC*CC, Wp + l*ZZ*5*CC,
            W_lin_s + l*CC*CC, W_lin_v + l*CC*CC, out, l);
    }
}

// round 9
// speedup vs baseline: 1.2034x; 1.2034x over previous
#include <cuda_runtime.h>
#include <math.h>

#define NN 50000
#define EE 800000
#define CC 32
#define ZZ 10
#define LL 2
#define NB 8
#define HH 64
#define INV_AVG (1.0f/16.0f)
#define RCUT_INV (1.0f/5.0f)

typedef unsigned long long u64;

// ---------------- scratch (static device globals; no allocation) -------------
__device__ float4 g_sv [NN*CC];   // {s, v0, v1, v2}
__device__ float4 g_up [NN*CC];   // {su, vu0, vu1, vu2}
__device__ float4 g_acc[NN*CC];   // {S, V0, V1, V2}
__device__ float4 g_Y1 [EE];      // {y0, y1, y2, pad}
__device__ float  g_ef [EE*NB];
__device__ int2   g_edge[EE];     // {src, dst}
__device__ int    g_z  [NN];

// ---------------- packed fp32x2 helpers (SASS FFMA2 via PTX) -----------------
__device__ __forceinline__ u64 pack2(float lo, float hi) {
    u64 r; asm("mov.b64 %0, {%1,%2};" : "=l"(r) : "f"(lo), "f"(hi)); return r;
}
__device__ __forceinline__ float2 unpk(u64 v) {
    float2 f; asm("mov.b64 {%0,%1}, %2;" : "=f"(f.x), "=f"(f.y) : "l"(v)); return f;
}
__device__ __forceinline__ void ffma2(u64 &d, u64 a, u64 b) {
    asm("fma.rn.f32x2 %0, %1, %2, %0;" : "+l"(d) : "l"(a), "l"(b));
}
__device__ __forceinline__ float silu(float x) {
    return __fdividef(x, 1.0f + __expf(-x));
}
__device__ __forceinline__ void red_v4(float4* p, float a, float b, float c, float d) {
    asm volatile("red.global.add.v4.f32 [%0], {%1,%2,%3,%4};"
                 :: "l"(p), "f"(a), "f"(b), "f"(c), "f"(d) : "memory");
}

// ---------------- species index from one-hot ---------------------------------
__global__ void k_zidx(const float* __restrict__ attrs) {
    int n = blockIdx.x * blockDim.x + threadIdx.x;
    if (n >= NN) return;
    int z = 0;
#pragma unroll
    for (int j = 0; j < ZZ; j++)
        if (attrs[n*ZZ + j] > 0.5f) z = j;
    g_z[n] = z;
}

// ---------------- s = onehot @ W_embed, v = 0 --------------------------------
__global__ void k_embed(const float* __restrict__ W_embed) {
    int idx = blockIdx.x * blockDim.x + threadIdx.x;
    if (idx >= NN*CC) return;
    int n = idx >> 5, c = idx & 31;
    g_sv[idx] = make_float4(W_embed[g_z[n]*CC + c], 0.f, 0.f, 0.f);
}

// ---------------- edge geometry: Y1 + radial features + packed index ---------
// NOTE: precise sinf per basis fn — fast-math trig here fails the 1e-3 gate.
__global__ void k_geom(const float* __restrict__ pos,
                       const float* __restrict__ shifts,
                       const int* __restrict__ src,
                       const int* __restrict__ dst) {
    int e = blockIdx.x * blockDim.x + threadIdx.x;
    if (e >= EE) return;
    int si = src[e], di = dst[e];
    g_edge[e] = make_int2(si, di);
    float vx = pos[di*3+0] - pos[si*3+0] + shifts[e*3+0];
    float vy = pos[di*3+1] - pos[si*3+1] + shifts[e*3+1];
    float vz = pos[di*3+2] - pos[si*3+2] + shifts[e*3+2];
    float r  = sqrtf(vx*vx + vy*vy + vz*vz);
    float rs = fmaxf(r, 1e-9f);
    float inv = 1.0f / rs;
    g_Y1[e] = make_float4(vx*inv, vy*inv, vz*inv, 0.f);
    float x = r * RCUT_INV;
    float fc = 0.f;
    if (x < 1.0f) {
        float x2 = x*x, x3 = x2*x;
        float x6 = x3*x3, x7 = x6*x, x8 = x7*x;
        fc = 1.0f - 28.0f*x6 + 48.0f*x7 - 21.0f*x8;   // P=6 polynomial cutoff
    }
    float coef = 0.6324555320336759f * fc * inv;       // sqrt(2/RCUT)*fc/rs
    float arg0 = rs * (float)M_PI * RCUT_INV;
#pragma unroll
    for (int nb = 0; nb < NB; nb++)
        g_ef[e*NB + nb] = coef * sinf((float)(nb+1) * arg0);
}

// ---------------- node "up" linears: su = s@Wus, vu = v@Wuv (+zero acc) ------
#define NWU 16
__global__ void k_nodeup(const float* __restrict__ Wus,
                         const float* __restrict__ Wuv) {
    __shared__ float sWs[CC*CC], sWv[CC*CC];
    __shared__ float st[NWU][128];
    int tid = threadIdx.x;
    for (int i = tid; i < CC*CC; i += blockDim.x) { sWs[i] = Wus[i]; sWv[i] = Wuv[i]; }
    __syncthreads();
    int warp = tid >> 5, lane = tid & 31;
    int n = blockIdx.x * NWU + warp;
    if (n >= NN) return;
    float* xs = st[warp];
    float* xv = st[warp] + 32;
    float4 f = g_sv[n*CC + lane];
    g_acc[n*CC + lane] = make_float4(0.f, 0.f, 0.f, 0.f);   // zero accumulators here
    xs[lane]       = f.x;
    xv[lane*3 + 0] = f.y;
    xv[lane*3 + 1] = f.z;
    xv[lane*3 + 2] = f.w;
    __syncwarp();
    float a = 0.f, u0 = 0.f, u1 = 0.f, u2 = 0.f;
#pragma unroll
    for (int k = 0; k < CC; k++) {
        float ws = sWs[k*CC + lane], wv = sWv[k*CC + lane];
        a  += xs[k]     * ws;
        u0 += xv[k*3+0] * wv;
        u1 += xv[k*3+1] * wv;
        u2 += xv[k*3+2] * wv;
    }
    g_up[n*CC + lane] = make_float4(a, u0, u1, u2);
}

// ---------------- fused edge kernel ------------------------------------------
// Phase A (lane = edge): radial MLP stages 1-2 with broadcast LDS.128 weights
//   and FFMA2 packed math; silu'd hidden written transposed to per-warp smem;
//   (src,dst) staged to per-warp smem.
// Phase B (lane = channel): stage-3 [64 -> 5x32] over TWO 16-edge halves
//   (acc[40] u64) — R3T swept 2x/batch. Epilogue in lean 4-edge groups to
//   keep transient registers off the accumulator peak.
#define EW 6
#define ETPB (EW*32)
#define HWF 2048          // 64*32 floats per warp
#define KP 68             // padded k stride (272B, conflict-free, 16B-aligned)

__global__ void __launch_bounds__(ETPB, 2)
k_edge(const float* __restrict__ R1,
       const float* __restrict__ R2,
       const float* __restrict__ R3) {
    extern __shared__ float smf[];
    float* sR1  = smf;                      // 512
    float* sR2  = sR1 + NB*HH;              // 4096
    float* sR3T = sR2 + HH*HH;              // 5*32*68 = 10880
    float* hall = sR3T + 5*CC*KP;           // EW*2048
    int2*  sdall = (int2*)(hall + EW*HWF);  // EW*32 int2
    int tid = threadIdx.x;
    for (int i = tid; i < NB*HH;   i += ETPB) sR1[i] = R1[i];
    for (int i = tid; i < HH*HH;   i += ETPB) sR2[i] = R2[i];
    for (int i = tid; i < 5*CC*HH; i += ETPB) {
        int k = i & 63, rest = i >> 6;
        int c = rest & 31, p = rest >> 5;
        sR3T[p*(CC*KP) + c*KP + k] = R3[k*5*CC + p*CC + c];
    }
    __syncthreads();

    int warp = tid >> 5, lane = tid & 31;
    float* hw  = hall + warp*HWF;
    int2*  sdw = sdall + warp*32;
    const int nbatch = EE/32;   // 25000, exact

    for (int b = blockIdx.x*EW + warp; b < nbatch; b += gridDim.x*EW) {
        int ebase = b*32;
        int e = ebase + lane;

        // ======== phase A: lane = edge ========
        sdw[lane] = __ldg(g_edge + e);          // stage (src,dst) for phase B
        float4 efa = *(const float4*)&g_ef[e*NB];
        float4 efb = *(const float4*)&g_ef[e*NB + 4];
        float ef[8] = {efa.x, efa.y, efa.z, efa.w, efb.x, efb.y, efb.z, efb.w};

        // stage 1: [8] -> [64]
        u64 h2[32];
#pragma unroll
        for (int m = 0; m < 32; m++) h2[m] = 0ull;
#pragma unroll
        for (int k = 0; k < 8; k++) {
            u64 a = pack2(ef[k], ef[k]);
            const ulonglong2* row = (const ulonglong2*)(sR1 + k*HH);
#pragma unroll
            for (int m = 0; m < 16; m++) {
                ulonglong2 w = row[m];
                ffma2(h2[2*m],   a, w.x);
                ffma2(h2[2*m+1], a, w.y);
            }
        }
#pragma unroll
        for (int m = 0; m < 32; m++) {
            float2 f = unpk(h2[m]);
            h2[m] = pack2(silu(f.x), silu(f.y));
        }

        // stage 2: [64] -> [64], split into two output halves (reg pressure)
#pragma unroll
        for (int Hh = 0; Hh < 2; Hh++) {
            u64 acc[16];
#pragma unroll
            for (int m = 0; m < 16; m++) acc[m] = 0ull;
#pragma unroll 4
            for (int kk = 0; kk < 32; kk++) {
                float2 hk = unpk(h2[kk]);
                u64 a0 = pack2(hk.x, hk.x);
                u64 a1 = pack2(hk.y, hk.y);
                const ulonglong2* r0 = (const ulonglong2*)(sR2 + (2*kk)*HH   + Hh*32);
                const ulonglong2* r1 = (const ulonglong2*)(sR2 + (2*kk+1)*HH + Hh*32);
#pragma unroll
                for (int m = 0; m < 8; m++) {
                    ulonglong2 w0 = r0[m], w1 = r1[m];
                    ffma2(acc[2*m],   a0, w0.x);
                    ffma2(acc[2*m+1], a0, w0.y);
                    ffma2(acc[2*m],   a1, w1.x);
                    ffma2(acc[2*m+1], a1, w1.y);
                }
            }
#pragma unroll
            for (int m = 0; m < 16; m++) {
                float2 f = unpk(acc[m]);
                hw[(Hh*32 + 2*m)*32   + lane] = silu(f.x);
                hw[(Hh*32 + 2*m+1)*32 + lane] = silu(f.y);
            }
        }
        __syncwarp();

        // ======== phase B: lane = channel, 2 halves of 16 edges ========
#pragma unroll 1
        for (int half = 0; half < 2; half++) {
            const float* hq = hw + half*16;
            u64 acc[40];   // [p][pair0..7]
#pragma unroll
            for (int i = 0; i < 40; i++) acc[i] = 0ull;
            const float* r3base = sR3T + lane*KP;
#pragma unroll 2
            for (int k4 = 0; k4 < 16; k4++) {
                float4 w40 = *(const float4*)(r3base + 0*(CC*KP) + 4*k4);
                float4 w41 = *(const float4*)(r3base + 1*(CC*KP) + 4*k4);
                float4 w42 = *(const float4*)(r3base + 2*(CC*KP) + 4*k4);
                float4 w43 = *(const float4*)(r3base + 3*(CC*KP) + 4*k4);
                float4 w44 = *(const float4*)(r3base + 4*(CC*KP) + 4*k4);
#pragma unroll
                for (int kk = 0; kk < 4; kk++) {
                    const float* hk = hq + (4*k4 + kk)*32;
                    ulonglong2 ha = *(const ulonglong2*)(hk);
                    ulonglong2 hb = *(const ulonglong2*)(hk + 4);
                    ulonglong2 hc = *(const ulonglong2*)(hk + 8);
                    ulonglong2 hd = *(const ulonglong2*)(hk + 12);
                    float w0 = (kk==0)?w40.x:(kk==1)?w40.y:(kk==2)?w40.z:w40.w;
                    float w1 = (kk==0)?w41.x:(kk==1)?w41.y:(kk==2)?w41.z:w41.w;
                    float w2 = (kk==0)?w42.x:(kk==1)?w42.y:(kk==2)?w42.z:w42.w;
                    float w3 = (kk==0)?w43.x:(kk==1)?w43.y:(kk==2)?w43.z:w43.w;
                    float w4 = (kk==0)?w44.x:(kk==1)?w44.y:(kk==2)?w44.z:w44.w;
                    u64 wp;
                    wp = pack2(w0, w0);
                    ffma2(acc[0],  ha.x, wp); ffma2(acc[1],  ha.y, wp);
                    ffma2(acc[2],  hb.x, wp); ffma2(acc[3],  hb.y, wp);
                    ffma2(acc[4],  hc.x, wp); ffma2(acc[5],  hc.y, wp);
                    ffma2(acc[6],  hd.x, wp); ffma2(acc[7],  hd.y, wp);
                    wp = pack2(w1, w1);
                    ffma2(acc[8],  ha.x, wp); ffma2(acc[9],  ha.y, wp);
                    ffma2(acc[10], hb.x, wp); ffma2(acc[11], hb.y, wp);
                    ffma2(acc[12], hc.x, wp); ffma2(acc[13], hc.y, wp);
                    ffma2(acc[14], hd.x, wp); ffma2(acc[15], hd.y, wp);
                    wp = pack2(w2, w2);
                    ffma2(acc[16], ha.x, wp); ffma2(acc[17], ha.y, wp);
                    ffma2(acc[18], hb.x, wp); ffma2(acc[19], hb.y, wp);
                    ffma2(acc[20], hc.x, wp); ffma2(acc[21], hc.y, wp);
                    ffma2(acc[22], hd.x, wp); ffma2(acc[23], hd.y, wp);
                    wp = pack2(w3, w3);
                    ffma2(acc[24], ha.x, wp); ffma2(acc[25], ha.y, wp);
                    ffma2(acc[26], hb.x, wp); ffma2(acc[27], hb.y, wp);
                    ffma2(acc[28], hc.x, wp); ffma2(acc[29], hc.y, wp);
                    ffma2(acc[30], hd.x, wp); ffma2(acc[31], hd.y, wp);
                    wp = pack2(w4, w4);
                    ffma2(acc[32], ha.x, wp); ffma2(acc[33], ha.y, wp);
                    ffma2(acc[34], hb.x, wp); ffma2(acc[35], hb.y, wp);
                    ffma2(acc[36], hc.x, wp); ffma2(acc[37], hc.y, wp);
                    ffma2(acc[38], hd.x, wp); ffma2(acc[39], hd.y, wp);
                }
            }

            // epilogue: 4 groups of 4 edges — lean transient register set
#pragma unroll 1
            for (int g = 0; g < 4; g++) {
                int jw0 = half*16 + g*4;
                int2   sd0 = sdw[jw0+0], sd1 = sdw[jw0+1], sd2 = sdw[jw0+2], sd3 = sdw[jw0+3];
                float4 y0v = __ldg(g_Y1 + ebase + jw0 + 0);
                float4 y1v = __ldg(g_Y1 + ebase + jw0 + 1);
                float4 y2v = __ldg(g_Y1 + ebase + jw0 + 2);
                float4 y3v = __ldg(g_Y1 + ebase + jw0 + 3);
                float4 u0v = __ldg(g_up + sd0.x*CC + lane);
                float4 u1v = __ldg(g_up + sd1.x*CC + lane);
                float4 u2v = __ldg(g_up + sd2.x*CC + lane);
                float4 u3v = __ldg(g_up + sd3.x*CC + lane);
#pragma unroll
                for (int j = 0; j < 4; j++) {
                    int jj = g*4 + j;               // within half: 0..15
                    int pair = jj >> 1, hh = jj & 1;
                    float2 a0 = unpk(acc[0*8+pair]);
                    float2 a1 = unpk(acc[1*8+pair]);
                    float2 a2 = unpk(acc[2*8+pair]);
                    float2 a3 = unpk(acc[3*8+pair]);
                    float2 a4 = unpk(acc[4*8+pair]);
                    float w0 = hh ? a0.y : a0.x;
                    float w1 = hh ? a1.y : a1.x;
                    float w2v= hh ? a2.y : a2.x;
                    float w3 = hh ? a3.y : a3.x;
                    float w4 = hh ? a4.y : a4.x;
                    float4 y4 = (j==0)?y0v:(j==1)?y1v:(j==2)?y2v:y3v;
                    float4 uv = (j==0)?u0v:(j==1)?u1v:(j==2)?u2v:u3v;
                    int    dI = (j==0)?sd0.y:(j==1)?sd1.y:(j==2)?sd2.y:sd3.y;
                    float y0 = y4.x, y1 = y4.y, y2 = y4.z;
                    float ss = uv.x, v0 = uv.y, v1 = uv.z, v2 = uv.w;
                    float dot = v0*y0 + v1*y1 + v2*y2;
                    float c0 = v1*y2 - v2*y1;
                    float c1 = v2*y0 - v0*y2;
                    float c2 = v0*y1 - v1*y0;
                    float ms = w0*ss + w3*dot;
                    float m0 = w1*ss*y0 + w2v*v0 + w4*c0;
                    float m1 = w1*ss*y1 + w2v*v1 + w4*c1;
                    float m2 = w1*ss*y2 + w2v*v2 + w4*c2;
                    red_v4(g_acc + dI*CC + lane, ms, m0, m1, m2);
                }
            }
        }
        __syncwarp();
    }
}

// ---------------- node update: out linears, skip, product block --------------
#define NWB 16
__global__ void k_nodeupd(const float* __restrict__ Wouts,
                          const float* __restrict__ Woutv,
                          const float* __restrict__ Wscs,
                          const float* __restrict__ Wscv,
                          const float* __restrict__ Wp,
                          const float* __restrict__ Wlins,
                          const float* __restrict__ Wlinv,
                          float* __restrict__ out, int l) {
    __shared__ float sWos[CC*CC], sWov[CC*CC], sWls[CC*CC], sWlv[CC*CC];
    __shared__ float st[NWB][256];
    int tid = threadIdx.x;
    for (int i = tid; i < CC*CC; i += blockDim.x) {
        sWos[i] = Wouts[i]; sWov[i] = Woutv[i];
        sWls[i] = Wlins[i]; sWlv[i] = Wlinv[i];
    }
    __syncthreads();
    int warp = tid >> 5, lane = tid & 31;
    int n = blockIdx.x * NWB + warp;
    if (n >= NN) return;

    float* xs = st[warp];
    float* xv = xs + 32;
    float* ys = xv + 96;
    float* yv = ys + 32;

    int z = g_z[n];
    float4 a4 = g_acc[n*CC + lane];
    float4 o4 = g_sv [n*CC + lane];
    xs[lane]       = a4.x * INV_AVG;
    xv[lane*3 + 0] = a4.y * INV_AVG;
    xv[lane*3 + 1] = a4.z * INV_AVG;
    xv[lane*3 + 2] = a4.w * INV_AVG;
    ys[lane]       = o4.x;
    yv[lane*3 + 0] = o4.y;
    yv[lane*3 + 1] = o4.z;
    yv[lane*3 + 2] = o4.w;
    __syncwarp();

    const float* Ws = Wscs + z*CC*CC;
    const float* Wv = Wscv + z*CC*CC;
    float s2 = 0.f, v20 = 0.f, v21 = 0.f, v22 = 0.f;
    float scs = 0.f, sv0 = 0.f, sv1 = 0.f, sv2 = 0.f;
#pragma unroll
    for (int k = 0; k < CC; k++) {
        float wo = sWos[k*CC + lane], wvv = sWov[k*CC + lane];
        s2  += xs[k]     * wo;
        v20 += xv[k*3+0] * wvv;
        v21 += xv[k*3+1] * wvv;
        v22 += xv[k*3+2] * wvv;
        float as = __ldg(Ws + k*CC + lane), av = __ldg(Wv + k*CC + lane);
        scs += ys[k]     * as;
        sv0 += yv[k*3+0] * av;
        sv1 += yv[k*3+1] * av;
        sv2 += yv[k*3+2] * av;
    }

    float we0 = __ldg(Wp + (z*5+0)*CC + lane);
    float we1 = __ldg(Wp + (z*5+1)*CC + lane);
    float we2 = __ldg(Wp + (z*5+2)*CC + lane);
    float we3 = __ldg(Wp + (z*5+3)*CC + lane);
    float we4 = __ldg(Wp + (z*5+4)*CC + lane);

    float vdot = v20*v20 + v21*v21 + v22*v22;
    float ps  = we0*s2 + we1*s2*s2 + we2*vdot;
    float pv0 = we3*v20 + we4*s2*v20;
    float pv1 = we3*v21 + we4*s2*v21;
    float pv2 = we3*v22 + we4*s2*v22;
    __syncwarp();
    xs[lane] = ps;
    xv[lane*3+0] = pv0; xv[lane*3+1] = pv1; xv[lane*3+2] = pv2;
    __syncwarp();

    float sn = scs, vn0 = sv0, vn1 = sv1, vn2 = sv2;
#pragma unroll
    for (int k = 0; k < CC; k++) {
        float wl = sWls[k*CC + lane], wlv = sWlv[k*CC + lane];
        sn  += xs[k]     * wl;
        vn0 += xv[k*3+0] * wlv;
        vn1 += xv[k*3+1] * wlv;
        vn2 += xv[k*3+2] * wlv;
    }
    g_sv[n*CC + lane] = make_float4(sn, vn0, vn1, vn2);
    out[n*(LL*CC) + l*CC + lane] = sn;
}

// ---------------- launch ------------------------------------------------------
extern "C" void kernel_launch(void* const* d_in, const int* in_sizes, int n_in,
                              void* d_out, int out_size) {
    const float* pos     = (const float*)d_in[0];
    const float* attrs   = (const float*)d_in[1];
    const float* shifts  = (const float*)d_in[2];
    const float* W_embed = (const float*)d_in[3];
    const float* W_up_s  = (const float*)d_in[4];
    const float* W_up_v  = (const float*)d_in[5];
    const float* R1      = (const float*)d_in[6];
    const float* R2      = (const float*)d_in[7];
    const float* R3      = (const float*)d_in[8];
    const float* W_out_s = (const float*)d_in[9];
    const float* W_out_v = (const float*)d_in[10];
    const float* Wsc_s   = (const float*)d_in[11];
    const float* Wsc_v   = (const float*)d_in[12];
    const float* Wp      = (const float*)d_in[13];
    const float* W_lin_s = (const float*)d_in[14];
    const float* W_lin_v = (const float*)d_in[15];
    const int*   ei      = (const int*)d_in[16];
    const int* src = ei;
    const int* dst = ei + EE;
    float* out = (float*)d_out;

    // floats: 15488 (weights) + EW*2048 (h) + EW*64 (int2 staging) = 28160
    int smem = (NB*HH + HH*HH + 5*CC*KP + EW*HWF + EW*64) * (int)sizeof(float); // 112640 B
    cudaFuncSetAttribute(k_edge, cudaFuncAttributeMaxDynamicSharedMemorySize, smem);

    k_zidx <<<(NN + 255)/256, 256>>>(attrs);
    k_embed<<<(NN*CC + 255)/256, 256>>>(W_embed);
    k_geom <<<(EE + 255)/256, 256>>>(pos, shifts, src, dst);

    for (int l = 0; l < LL; l++) {
        k_nodeup<<<(NN + NWU - 1)/NWU, NWU*32>>>(W_up_s + l*CC*CC, W_up_v + l*CC*CC);
        k_edge  <<<296, ETPB, smem>>>(R1 + l*NB*HH, R2 + l*HH*HH, R3 + l*HH*5*CC);
        k_nodeupd<<<(NN + NWB - 1)/NWB, NWB*32>>>(
            W_out_s + l*CC*CC, W_out_v + l*CC*CC,
            Wsc_s + l*ZZ*CC*CC, Wsc_v + l*ZZ*CC*CC, Wp + l*ZZ*5*CC,
            W_lin_s + l*CC*CC, W_lin_v + l*CC*CC, out, l);
    }
}

// round 10
// speedup vs baseline: 1.4020x; 1.1650x over previous
#include <cuda_runtime.h>
#include <math.h>

#define NN 50000
#define EE 800000
#define CC 32
#define ZZ 10
#define LL 2
#define NB 8
#define HH 64
#define INV_AVG (1.0f/16.0f)
#define RCUT_INV (1.0f/5.0f)

typedef unsigned long long u64;

// ---------------- scratch (static device globals; no allocation) -------------
__device__ float4 g_sv [NN*CC];   // {s, v0, v1, v2}
__device__ float4 g_up [NN*CC];   // {su, vu0, vu1, vu2}
__device__ float4 g_acc[NN*CC];   // {S, V0, V1, V2}
__device__ float4 g_Y1 [EE];      // {y0, y1, y2, pad}
__device__ float  g_ef [EE*NB];
__device__ int2   g_edge[EE];     // {src, dst}
__device__ int    g_z  [NN];
__device__ float  g_su0[ZZ*CC];   // layer-0 su table (species-only)

// ---------------- packed fp32x2 helpers (SASS FFMA2 via PTX) -----------------
__device__ __forceinline__ u64 pack2(float lo, float hi) {
    u64 r; asm("mov.b64 %0, {%1,%2};" : "=l"(r) : "f"(lo), "f"(hi)); return r;
}
__device__ __forceinline__ float2 unpk(u64 v) {
    float2 f; asm("mov.b64 {%0,%1}, %2;" : "=f"(f.x), "=f"(f.y) : "l"(v)); return f;
}
__device__ __forceinline__ void ffma2(u64 &d, u64 a, u64 b) {
    asm("fma.rn.f32x2 %0, %1, %2, %0;" : "+l"(d) : "l"(a), "l"(b));
}
__device__ __forceinline__ float silu(float x) {
    return __fdividef(x, 1.0f + __expf(-x));
}
__device__ __forceinline__ void red_v4(float4* p, float a, float b, float c, float d) {
    asm volatile("red.global.add.v4.f32 [%0], {%1,%2,%3,%4};"
                 :: "l"(p), "f"(a), "f"(b), "f"(c), "f"(d) : "memory");
}

// ---------------- species index from one-hot ---------------------------------
__global__ void k_zidx(const float* __restrict__ attrs) {
    int n = blockIdx.x * blockDim.x + threadIdx.x;
    if (n >= NN) return;
    int z = 0;
#pragma unroll
    for (int j = 0; j < ZZ; j++)
        if (attrs[n*ZZ + j] > 0.5f) z = j;
    g_z[n] = z;
}

// ---------------- layer-0 su table: su0[z] = W_embed[z] @ W_up_s[0] ----------
__global__ void k_pre0(const float* __restrict__ W_embed,
                       const float* __restrict__ Wus) {
    int z = threadIdx.x >> 5, lane = threadIdx.x & 31;
    if (z >= ZZ) return;
    float a = 0.f;
#pragma unroll
    for (int k = 0; k < CC; k++)
        a += W_embed[z*CC + k] * Wus[k*CC + lane];
    g_su0[z*CC + lane] = a;
}

// ---------------- fused init: s=embed, v=0, up from table, acc=0 -------------
__global__ void k_init0(const float* __restrict__ W_embed) {
    int idx = blockIdx.x * blockDim.x + threadIdx.x;
    if (idx >= NN*CC) return;
    int n = idx >> 5, c = idx & 31;
    int z = g_z[n];
    g_sv [idx] = make_float4(W_embed[z*CC + c], 0.f, 0.f, 0.f);
    g_up [idx] = make_float4(g_su0[z*CC + c],   0.f, 0.f, 0.f);
    g_acc[idx] = make_float4(0.f, 0.f, 0.f, 0.f);
}

// ---------------- edge geometry: Y1 + radial features + packed index ---------
// NOTE: precise sinf per basis fn — fast-math trig here fails the 1e-3 gate.
__global__ void k_geom(const float* __restrict__ pos,
                       const float* __restrict__ shifts,
                       const int* __restrict__ src,
                       const int* __restrict__ dst) {
    int e = blockIdx.x * blockDim.x + threadIdx.x;
    if (e >= EE) return;
    int si = src[e], di = dst[e];
    g_edge[e] = make_int2(si, di);
    float vx = pos[di*3+0] - pos[si*3+0] + shifts[e*3+0];
    float vy = pos[di*3+1] - pos[si*3+1] + shifts[e*3+1];
    float vz = pos[di*3+2] - pos[si*3+2] + shifts[e*3+2];
    float r  = sqrtf(vx*vx + vy*vy + vz*vz);
    float rs = fmaxf(r, 1e-9f);
    float inv = 1.0f / rs;
    g_Y1[e] = make_float4(vx*inv, vy*inv, vz*inv, 0.f);
    float x = r * RCUT_INV;
    float fc = 0.f;
    if (x < 1.0f) {
        float x2 = x*x, x3 = x2*x;
        float x6 = x3*x3, x7 = x6*x, x8 = x7*x;
        fc = 1.0f - 28.0f*x6 + 48.0f*x7 - 21.0f*x8;   // P=6 polynomial cutoff
    }
    float coef = 0.6324555320336759f * fc * inv;       // sqrt(2/RCUT)*fc/rs
    float arg0 = rs * (float)M_PI * RCUT_INV;
#pragma unroll
    for (int nb = 0; nb < NB; nb++)
        g_ef[e*NB + nb] = coef * sinf((float)(nb+1) * arg0);
}

// ---------------- fused edge kernel ------------------------------------------
// Phase A (lane = edge): radial MLP stages 1-2, FFMA2 packed, broadcast LDS.128
//   weights; silu'd hidden written transposed to per-warp smem.
// Phase B (lane = channel): stage-3 over 4 sub-batches of 8 edges (PROVEN
//   tiling). NP = number of TP paths: 2 for layer 0 (v==0 → paths 2,3,4 are
//   exactly zero), 5 for general layers.
#define EW 6
#define ETPB (EW*32)
#define HWF 2048          // 64*32 floats per warp
#define KP 68             // padded k stride (272B, conflict-free, 16B-aligned)

template<int NP>
__global__ void __launch_bounds__(ETPB, 2)
k_edge(const float* __restrict__ R1,
       const float* __restrict__ R2,
       const float* __restrict__ R3) {
    extern __shared__ float smf[];
    float* sR1  = smf;                      // 512
    float* sR2  = sR1 + NB*HH;              // 4096
    float* sR3T = sR2 + HH*HH;              // 5*32*68 (NP planes used)
    float* hall = sR3T + 5*CC*KP;           // EW*2048
    int tid = threadIdx.x;
    for (int i = tid; i < NB*HH;    i += ETPB) sR1[i] = R1[i];
    for (int i = tid; i < HH*HH;    i += ETPB) sR2[i] = R2[i];
    for (int i = tid; i < NP*CC*HH; i += ETPB) {
        int k = i & 63, rest = i >> 6;
        int c = rest & 31, p = rest >> 5;
        sR3T[p*(CC*KP) + c*KP + k] = R3[k*5*CC + p*CC + c];
    }
    __syncthreads();

    int warp = tid >> 5, lane = tid & 31;
    float* hw = hall + warp*HWF;
    const int nbatch = EE/32;   // 25000, exact

    for (int b = blockIdx.x*EW + warp; b < nbatch; b += gridDim.x*EW) {
        int ebase = b*32;
        int e = ebase + lane;

        // ======== phase A: lane = edge ========
        float4 efa = *(const float4*)&g_ef[e*NB];
        float4 efb = *(const float4*)&g_ef[e*NB + 4];
        float ef[8] = {efa.x, efa.y, efa.z, efa.w, efb.x, efb.y, efb.z, efb.w};

        // stage 1: [8] -> [64]
        u64 h2[32];
#pragma unroll
        for (int m = 0; m < 32; m++) h2[m] = 0ull;
#pragma unroll
        for (int k = 0; k < 8; k++) {
            u64 a = pack2(ef[k], ef[k]);
            const ulonglong2* row = (const ulonglong2*)(sR1 + k*HH);
#pragma unroll
            for (int m = 0; m < 16; m++) {
                ulonglong2 w = row[m];
                ffma2(h2[2*m],   a, w.x);
                ffma2(h2[2*m+1], a, w.y);
            }
        }
#pragma unroll
        for (int m = 0; m < 32; m++) {
            float2 f = unpk(h2[m]);
            h2[m] = pack2(silu(f.x), silu(f.y));
        }

        // stage 2: [64] -> [64], split into two output halves (reg pressure)
#pragma unroll
        for (int Hh = 0; Hh < 2; Hh++) {
            u64 acc[16];
#pragma unroll
            for (int m = 0; m < 16; m++) acc[m] = 0ull;
#pragma unroll 4
            for (int kk = 0; kk < 32; kk++) {
                float2 hk = unpk(h2[kk]);
                u64 a0 = pack2(hk.x, hk.x);
                u64 a1 = pack2(hk.y, hk.y);
                const ulonglong2* r0 = (const ulonglong2*)(sR2 + (2*kk)*HH   + Hh*32);
                const ulonglong2* r1 = (const ulonglong2*)(sR2 + (2*kk+1)*HH + Hh*32);
#pragma unroll
                for (int m = 0; m < 8; m++) {
                    ulonglong2 w0 = r0[m], w1 = r1[m];
                    ffma2(acc[2*m],   a0, w0.x);
                    ffma2(acc[2*m+1], a0, w0.y);
                    ffma2(acc[2*m],   a1, w1.x);
                    ffma2(acc[2*m+1], a1, w1.y);
                }
            }
#pragma unroll
            for (int m = 0; m < 16; m++) {
                float2 f = unpk(acc[m]);
                hw[(Hh*32 + 2*m)*32   + lane] = silu(f.x);
                hw[(Hh*32 + 2*m+1)*32 + lane] = silu(f.y);
            }
        }
        __syncwarp();

        // ======== phase B: lane = channel, 4 sub-batches of 8 edges ========
#pragma unroll 1
        for (int q = 0; q < 4; q++) {
            // hoisted gathers (overlap with k-loop)
            int eg0 = ebase + q*8;
            float4 uv8[8];
            float  yx[8], yy[8], yz[8];
            int    d8[8];
#pragma unroll
            for (int j = 0; j < 8; j++) {
                int2 sd = __ldg(g_edge + eg0 + j);
                d8[j] = sd.y;
                float4 y4 = __ldg(g_Y1 + eg0 + j);
                yx[j] = y4.x; yy[j] = y4.y; yz[j] = y4.z;
                uv8[j] = __ldg(g_up + sd.x*CC + lane);
            }

            u64 acc[NP*4];   // [p][pair]
#pragma unroll
            for (int i = 0; i < NP*4; i++) acc[i] = 0ull;
            const float* hq = hw + q*8;
            const float* r3base = sR3T + lane*KP;
#pragma unroll 2
            for (int k4 = 0; k4 < 16; k4++) {
                ulonglong2 hA[4], hB[4];
#pragma unroll
                for (int kk = 0; kk < 4; kk++) {
                    hA[kk] = *(const ulonglong2*)(hq + (4*k4+kk)*32);
                    hB[kk] = *(const ulonglong2*)(hq + (4*k4+kk)*32 + 4);
                }
#pragma unroll
                for (int p = 0; p < NP; p++) {
                    float4 w4 = *(const float4*)(r3base + p*(CC*KP) + 4*k4);
                    float wv[4] = {w4.x, w4.y, w4.z, w4.w};
#pragma unroll
                    for (int kk = 0; kk < 4; kk++) {
                        u64 w2 = pack2(wv[kk], wv[kk]);
                        ffma2(acc[p*4+0], hA[kk].x, w2);
                        ffma2(acc[p*4+1], hA[kk].y, w2);
                        ffma2(acc[p*4+2], hB[kk].x, w2);
                        ffma2(acc[p*4+3], hB[kk].y, w2);
                    }
                }
            }

            // TP message + vec4 atomic scatter for 8 edges
#pragma unroll
            for (int pr = 0; pr < 4; pr++) {
                float2 w0p = unpk(acc[0*4+pr]);
                float2 w1p = unpk(acc[1*4+pr]);
#pragma unroll
                for (int hh = 0; hh < 2; hh++) {
                    int j = pr*2 + hh;
                    float w0 = hh ? w0p.y : w0p.x;
                    float w1 = hh ? w1p.y : w1p.x;
                    float y0 = yx[j], y1 = yy[j], y2 = yz[j];
                    float ss = uv8[j].x;
                    float ms, m0, m1, m2;
                    if (NP == 2) {
                        // layer 0: v==0 → only paths 0 (scalar) and 1 (s*Y1)
                        ms = w0*ss;
                        float w1s = w1*ss;
                        m0 = w1s*y0; m1 = w1s*y1; m2 = w1s*y2;
                    } else {
                        float2 w2p = unpk(acc[2*4+pr]);
                        float2 w3p = unpk(acc[3*4+pr]);
                        float2 w4p = unpk(acc[4*4+pr]);
                        float w2v = hh ? w2p.y : w2p.x;
                        float w3  = hh ? w3p.y : w3p.x;
                        float w4  = hh ? w4p.y : w4p.x;
                        float v0 = uv8[j].y, v1 = uv8[j].z, v2 = uv8[j].w;
                        float dot = v0*y0 + v1*y1 + v2*y2;
                        float c0 = v1*y2 - v2*y1;
                        float c1 = v2*y0 - v0*y2;
                        float c2 = v0*y1 - v1*y0;
                        ms = w0*ss + w3*dot;
                        m0 = w1*ss*y0 + w2v*v0 + w4*c0;
                        m1 = w1*ss*y1 + w2v*v1 + w4*c1;
                        m2 = w1*ss*y2 + w2v*v2 + w4*c2;
                    }
                    red_v4(g_acc + d8[j]*CC + lane, ms, m0, m1, m2);
                }
            }
        }
        __syncwarp();
    }
}

// ---------------- node update: out linears, skip, product block --------------
// FUSE: additionally compute next layer's up-projection (su,vu) and zero acc.
#define NWB 16
template<bool FUSE>
__global__ void k_nodeupd(const float* __restrict__ Wouts,
                          const float* __restrict__ Woutv,
                          const float* __restrict__ Wscs,
                          const float* __restrict__ Wscv,
                          const float* __restrict__ Wp,
                          const float* __restrict__ Wlins,
                          const float* __restrict__ Wlinv,
                          const float* __restrict__ WusN,
                          const float* __restrict__ WuvN,
                          float* __restrict__ out, int l) {
    __shared__ float sWos[CC*CC], sWov[CC*CC], sWls[CC*CC], sWlv[CC*CC];
    __shared__ float sWus[CC*CC], sWuv[CC*CC];
    __shared__ float st[NWB][256];
    int tid = threadIdx.x;
    for (int i = tid; i < CC*CC; i += blockDim.x) {
        sWos[i] = Wouts[i]; sWov[i] = Woutv[i];
        sWls[i] = Wlins[i]; sWlv[i] = Wlinv[i];
        if (FUSE) { sWus[i] = WusN[i]; sWuv[i] = WuvN[i]; }
    }
    __syncthreads();
    int warp = tid >> 5, lane = tid & 31;
    int n = blockIdx.x * NWB + warp;
    if (n >= NN) return;

    float* xs = st[warp];
    float* xv = xs + 32;
    float* ys = xv + 96;
    float* yv = ys + 32;

    int z = g_z[n];
    float4 a4 = g_acc[n*CC + lane];
    float4 o4 = g_sv [n*CC + lane];
    xs[lane]       = a4.x * INV_AVG;
    xv[lane*3 + 0] = a4.y * INV_AVG;
    xv[lane*3 + 1] = a4.z * INV_AVG;
    xv[lane*3 + 2] = a4.w * INV_AVG;
    ys[lane]       = o4.x;
    yv[lane*3 + 0] = o4.y;
    yv[lane*3 + 1] = o4.z;
    yv[lane*3 + 2] = o4.w;
    __syncwarp();

    const float* Ws = Wscs + z*CC*CC;
    const float* Wv = Wscv + z*CC*CC;
    float s2 = 0.f, v20 = 0.f, v21 = 0.f, v22 = 0.f;
    float scs = 0.f, sv0 = 0.f, sv1 = 0.f, sv2 = 0.f;
#pragma unroll
    for (int k = 0; k < CC; k++) {
        float wo = sWos[k*CC + lane], wvv = sWov[k*CC + lane];
        s2  += xs[k]     * wo;
        v20 += xv[k*3+0] * wvv;
        v21 += xv[k*3+1] * wvv;
        v22 += xv[k*3+2] * wvv;
        float as = __ldg(Ws + k*CC + lane), av = __ldg(Wv + k*CC + lane);
        scs += ys[k]     * as;
        sv0 += yv[k*3+0] * av;
        sv1 += yv[k*3+1] * av;
        sv2 += yv[k*3+2] * av;
    }

    float we0 = __ldg(Wp + (z*5+0)*CC + lane);
    float we1 = __ldg(Wp + (z*5+1)*CC + lane);
    float we2 = __ldg(Wp + (z*5+2)*CC + lane);
    float we3 = __ldg(Wp + (z*5+3)*CC + lane);
    float we4 = __ldg(Wp + (z*5+4)*CC + lane);

    float vdot = v20*v20 + v21*v21 + v22*v22;
    float ps  = we0*s2 + we1*s2*s2 + we2*vdot;
    float pv0 = we3*v20 + we4*s2*v20;
    float pv1 = we3*v21 + we4*s2*v21;
    float pv2 = we3*v22 + we4*s2*v22;
    __syncwarp();
    xs[lane] = ps;
    xv[lane*3+0] = pv0; xv[lane*3+1] = pv1; xv[lane*3+2] = pv2;
    __syncwarp();

    float sn = scs, vn0 = sv0, vn1 = sv1, vn2 = sv2;
#pragma unroll
    for (int k = 0; k < CC; k++) {
        float wl = sWls[k*CC + lane], wlv = sWlv[k*CC + lane];
        sn  += xs[k]     * wl;
        vn0 += xv[k*3+0] * wlv;
        vn1 += xv[k*3+1] * wlv;
        vn2 += xv[k*3+2] * wlv;
    }
    g_sv[n*CC + lane] = make_float4(sn, vn0, vn1, vn2);
    out[n*(LL*CC) + l*CC + lane] = sn;

    if (FUSE) {
        // next layer's up-projection from fresh (sn, vn) + zero accumulators
        __syncwarp();
        ys[lane]       = sn;
        yv[lane*3 + 0] = vn0;
        yv[lane*3 + 1] = vn1;
        yv[lane*3 + 2] = vn2;
        __syncwarp();
        float a = 0.f, u0 = 0.f, u1 = 0.f, u2 = 0.f;
#pragma unroll
        for (int k = 0; k < CC; k++) {
            float ws = sWus[k*CC + lane], wv = sWuv[k*CC + lane];
            a  += ys[k]     * ws;
            u0 += yv[k*3+0] * wv;
            u1 += yv[k*3+1] * wv;
            u2 += yv[k*3+2] * wv;
        }
        g_up [n*CC + lane] = make_float4(a, u0, u1, u2);
        g_acc[n*CC + lane] = make_float4(0.f, 0.f, 0.f, 0.f);
    }
}

// ---------------- launch ------------------------------------------------------
extern "C" void kernel_launch(void* const* d_in, const int* in_sizes, int n_in,
                              void* d_out, int out_size) {
    const float* pos     = (const float*)d_in[0];
    const float* attrs   = (const float*)d_in[1];
    const float* shifts  = (const float*)d_in[2];
    const float* W_embed = (const float*)d_in[3];
    const float* W_up_s  = (const float*)d_in[4];
    const float* W_up_v  = (const float*)d_in[5];
    const float* R1      = (const float*)d_in[6];
    const float* R2      = (const float*)d_in[7];
    const float* R3      = (const float*)d_in[8];
    const float* W_out_s = (const float*)d_in[9];
    const float* W_out_v = (const float*)d_in[10];
    const float* Wsc_s   = (const float*)d_in[11];
    const float* Wsc_v   = (const float*)d_in[12];
    const float* Wp      = (const float*)d_in[13];
    const float* W_lin_s = (const float*)d_in[14];
    const float* W_lin_v = (const float*)d_in[15];
    const int*   ei      = (const int*)d_in[16];
    const int* src = ei;
    const int* dst = ei + EE;
    float* out = (float*)d_out;

    int smem = (NB*HH + HH*HH + 5*CC*KP + EW*HWF) * (int)sizeof(float); // 111104 B
    cudaFuncSetAttribute(k_edge<2>, cudaFuncAttributeMaxDynamicSharedMemorySize, smem);
    cudaFuncSetAttribute(k_edge<5>, cudaFuncAttributeMaxDynamicSharedMemorySize, smem);

    k_zidx <<<(NN + 255)/256, 256>>>(attrs);
    k_pre0 <<<1, ZZ*32>>>(W_embed, W_up_s);
    k_init0<<<(NN*CC + 255)/256, 256>>>(W_embed);
    k_geom <<<(EE + 255)/256, 256>>>(pos, shifts, src, dst);

    // layer 0 (v == 0 → 2-path edge kernel; nodeupd fuses layer-1 up-proj)
    k_edge<2><<<296, ETPB, smem>>>(R1, R2, R3);
    k_nodeupd<true><<<(NN + NWB - 1)/NWB, NWB*32>>>(
        W_out_s, W_out_v, Wsc_s, Wsc_v, Wp, W_lin_s, W_lin_v,
        W_up_s + CC*CC, W_up_v + CC*CC, out, 0);

    // layer 1 (full 5-path edge kernel)
    k_edge<5><<<296, ETPB, smem>>>(R1 + NB*HH, R2 + HH*HH, R3 + HH*5*CC);
    k_nodeupd<false><<<(NN + NWB - 1)/NWB, NWB*32>>>(
        W_out_s + CC*CC, W_out_v + CC*CC,
        Wsc_s + ZZ*CC*CC, Wsc_v + ZZ*CC*CC, Wp + ZZ*5*CC,
        W_lin_s + CC*CC, W_lin_v + CC*CC,
        W_up_s, W_up_v, out, 1);
}

// round 11
// speedup vs baseline: 1.4130x; 1.0079x over previous
#include <cuda_runtime.h>
#include <math.h>

#define NN 50000
#define EE 800000
#define CC 32
#define ZZ 10
#define LL 2
#define NB 8
#define HH 64
#define INV_AVG (1.0f/16.0f)
#define RCUT_INV (1.0f/5.0f)

typedef unsigned long long u64;

// ---------------- scratch (static device globals; no allocation) -------------
__device__ float4 g_sv [NN*CC];   // {s, v0, v1, v2}
__device__ float4 g_up [NN*CC];   // {su, vu0, vu1, vu2}
__device__ float4 g_acc[NN*CC];   // {S, V0, V1, V2}
__device__ float4 g_Y1 [EE];      // {y0, y1, y2, pad}
__device__ float  g_ef [EE*NB];
__device__ int2   g_edge [EE];    // {src, dst}   (layer >= 1)
__device__ int2   g_edge0[EE];    // {z[src], dst} (layer 0)
__device__ int    g_z  [NN];
__device__ float  g_su0[ZZ*CC];   // layer-0 su table (species-only)

// ---------------- packed fp32x2 helpers (SASS FFMA2 via PTX) -----------------
__device__ __forceinline__ u64 pack2(float lo, float hi) {
    u64 r; asm("mov.b64 %0, {%1,%2};" : "=l"(r) : "f"(lo), "f"(hi)); return r;
}
__device__ __forceinline__ float2 unpk(u64 v) {
    float2 f; asm("mov.b64 {%0,%1}, %2;" : "=f"(f.x), "=f"(f.y) : "l"(v)); return f;
}
__device__ __forceinline__ void ffma2(u64 &d, u64 a, u64 b) {
    asm("fma.rn.f32x2 %0, %1, %2, %0;" : "+l"(d) : "l"(a), "l"(b));
}
__device__ __forceinline__ float silu(float x) {
    return __fdividef(x, 1.0f + __expf(-x));
}
__device__ __forceinline__ void red_v4(float4* p, float a, float b, float c, float d) {
    asm volatile("red.global.add.v4.f32 [%0], {%1,%2,%3,%4};"
                 :: "l"(p), "f"(a), "f"(b), "f"(c), "f"(d) : "memory");
}

// ---------------- species index from one-hot ---------------------------------
__global__ void k_zidx(const float* __restrict__ attrs) {
    int n = blockIdx.x * blockDim.x + threadIdx.x;
    if (n >= NN) return;
    int z = 0;
#pragma unroll
    for (int j = 0; j < ZZ; j++)
        if (attrs[n*ZZ + j] > 0.5f) z = j;
    g_z[n] = z;
}

// ---------------- layer-0 su table: su0[z] = W_embed[z] @ W_up_s[0] ----------
__global__ void k_pre0(const float* __restrict__ W_embed,
                       const float* __restrict__ Wus) {
    int z = threadIdx.x >> 5, lane = threadIdx.x & 31;
    if (z >= ZZ) return;
    float a = 0.f;
#pragma unroll
    for (int k = 0; k < CC; k++)
        a += W_embed[z*CC + k] * Wus[k*CC + lane];
    g_su0[z*CC + lane] = a;
}

// ---------------- fused init: s=embed, v=0, up from table, acc=0 -------------
__global__ void k_init0(const float* __restrict__ W_embed) {
    int idx = blockIdx.x * blockDim.x + threadIdx.x;
    if (idx >= NN*CC) return;
    int n = idx >> 5, c = idx & 31;
    int z = g_z[n];
    g_sv [idx] = make_float4(W_embed[z*CC + c], 0.f, 0.f, 0.f);
    g_up [idx] = make_float4(g_su0[z*CC + c],   0.f, 0.f, 0.f);
    g_acc[idx] = make_float4(0.f, 0.f, 0.f, 0.f);
}

// ---------------- edge geometry: Y1 + radial features + packed indices -------
// NOTE: precise sinf per basis fn — fast-math trig here fails the 1e-3 gate.
__global__ void k_geom(const float* __restrict__ pos,
                       const float* __restrict__ shifts,
                       const int* __restrict__ src,
                       const int* __restrict__ dst) {
    int e = blockIdx.x * blockDim.x + threadIdx.x;
    if (e >= EE) return;
    int si = src[e], di = dst[e];
    g_edge [e] = make_int2(si, di);
    g_edge0[e] = make_int2(__ldg(g_z + si), di);   // layer-0 uses species of src
    float vx = pos[di*3+0] - pos[si*3+0] + shifts[e*3+0];
    float vy = pos[di*3+1] - pos[si*3+1] + shifts[e*3+1];
    float vz = pos[di*3+2] - pos[si*3+2] + shifts[e*3+2];
    float r  = sqrtf(vx*vx + vy*vy + vz*vz);
    float rs = fmaxf(r, 1e-9f);
    float inv = 1.0f / rs;
    g_Y1[e] = make_float4(vx*inv, vy*inv, vz*inv, 0.f);
    float x = r * RCUT_INV;
    float fc = 0.f;
    if (x < 1.0f) {
        float x2 = x*x, x3 = x2*x;
        float x6 = x3*x3, x7 = x6*x, x8 = x7*x;
        fc = 1.0f - 28.0f*x6 + 48.0f*x7 - 21.0f*x8;   // P=6 polynomial cutoff
    }
    float coef = 0.6324555320336759f * fc * inv;       // sqrt(2/RCUT)*fc/rs
    float arg0 = rs * (float)M_PI * RCUT_INV;
#pragma unroll
    for (int nb = 0; nb < NB; nb++)
        g_ef[e*NB + nb] = coef * sinf((float)(nb+1) * arg0);
}

// ---------------- fused edge kernel ------------------------------------------
// Phase A (lane = edge): radial MLP stages 1-2, FFMA2 packed, broadcast LDS.128
//   weights; silu'd hidden written transposed to per-warp smem.
// Phase B (lane = channel): stage-3 over 4 sub-batches of 8 edges (PROVEN
//   tiling). NP=2 (layer 0): v==0 → paths 2,3,4 exactly zero AND ss comes from
//   the 10x32 su0 table in smem — no g_up gathers at all.
#define EW 6
#define ETPB (EW*32)
#define HWF 2048          // 64*32 floats per warp
#define KP 68             // padded k stride (272B, 16B-aligned)

template<int NP>
__global__ void __launch_bounds__(ETPB, 2)
k_edge(const float* __restrict__ R1,
       const float* __restrict__ R2,
       const float* __restrict__ R3) {
    extern __shared__ float smf[];
    float* sR1  = smf;                      // 512
    float* sR2  = sR1 + NB*HH;              // 4096
    float* sR3T = sR2 + HH*HH;              // 5*32*68 (NP planes used)
    float* hall = sR3T + 5*CC*KP;           // EW*2048
    float* sSU0 = hall + EW*HWF;            // ZZ*CC (layer 0 only)
    int tid = threadIdx.x;
    for (int i = tid; i < NB*HH;    i += ETPB) sR1[i] = R1[i];
    for (int i = tid; i < HH*HH;    i += ETPB) sR2[i] = R2[i];
    for (int i = tid; i < NP*CC*HH; i += ETPB) {
        int k = i & 63, rest = i >> 6;
        int c = rest & 31, p = rest >> 5;
        sR3T[p*(CC*KP) + c*KP + k] = R3[k*5*CC + p*CC + c];
    }
    if (NP == 2)
        for (int i = tid; i < ZZ*CC; i += ETPB) sSU0[i] = g_su0[i];
    __syncthreads();

    int warp = tid >> 5, lane = tid & 31;
    float* hw = hall + warp*HWF;
    const int nbatch = EE/32;   // 25000, exact

    for (int b = blockIdx.x*EW + warp; b < nbatch; b += gridDim.x*EW) {
        int ebase = b*32;
        int e = ebase + lane;

        // ======== phase A: lane = edge ========
        float4 efa = *(const float4*)&g_ef[e*NB];
        float4 efb = *(const float4*)&g_ef[e*NB + 4];
        float ef[8] = {efa.x, efa.y, efa.z, efa.w, efb.x, efb.y, efb.z, efb.w};

        // stage 1: [8] -> [64]
        u64 h2[32];
#pragma unroll
        for (int m = 0; m < 32; m++) h2[m] = 0ull;
#pragma unroll
        for (int k = 0; k < 8; k++) {
            u64 a = pack2(ef[k], ef[k]);
            const ulonglong2* row = (const ulonglong2*)(sR1 + k*HH);
#pragma unroll
            for (int m = 0; m < 16; m++) {
                ulonglong2 w = row[m];
                ffma2(h2[2*m],   a, w.x);
                ffma2(h2[2*m+1], a, w.y);
            }
        }
#pragma unroll
        for (int m = 0; m < 32; m++) {
            float2 f = unpk(h2[m]);
            h2[m] = pack2(silu(f.x), silu(f.y));
        }

        // stage 2: [64] -> [64], split into two output halves (reg pressure)
#pragma unroll
        for (int Hh = 0; Hh < 2; Hh++) {
            u64 acc[16];
#pragma unroll
            for (int m = 0; m < 16; m++) acc[m] = 0ull;
#pragma unroll 4
            for (int kk = 0; kk < 32; kk++) {
                float2 hk = unpk(h2[kk]);
                u64 a0 = pack2(hk.x, hk.x);
                u64 a1 = pack2(hk.y, hk.y);
                const ulonglong2* r0 = (const ulonglong2*)(sR2 + (2*kk)*HH   + Hh*32);
                const ulonglong2* r1 = (const ulonglong2*)(sR2 + (2*kk+1)*HH + Hh*32);
#pragma unroll
                for (int m = 0; m < 8; m++) {
                    ulonglong2 w0 = r0[m], w1 = r1[m];
                    ffma2(acc[2*m],   a0, w0.x);
                    ffma2(acc[2*m+1], a0, w0.y);
                    ffma2(acc[2*m],   a1, w1.x);
                    ffma2(acc[2*m+1], a1, w1.y);
                }
            }
#pragma unroll
            for (int m = 0; m < 16; m++) {
                float2 f = unpk(acc[m]);
                hw[(Hh*32 + 2*m)*32   + lane] = silu(f.x);
                hw[(Hh*32 + 2*m+1)*32 + lane] = silu(f.y);
            }
        }
        __syncwarp();

        // ======== phase B: lane = channel, 4 sub-batches of 8 edges ========
#pragma unroll 1
        for (int q = 0; q < 4; q++) {
            // hoisted gathers (overlap with k-loop)
            int eg0 = ebase + q*8;
            float4 uv8[8];
            int    zs8[8];
            float  yx[8], yy[8], yz[8];
            int    d8[8];
#pragma unroll
            for (int j = 0; j < 8; j++) {
                int2 sd = __ldg((NP == 2 ? g_edge0 : g_edge) + eg0 + j);
                d8[j] = sd.y;
                float4 y4 = __ldg(g_Y1 + eg0 + j);
                yx[j] = y4.x; yy[j] = y4.y; yz[j] = y4.z;
                if (NP == 2) zs8[j] = sd.x;
                else         uv8[j] = __ldg(g_up + sd.x*CC + lane);
            }

            u64 acc[NP*4];   // [p][pair]
#pragma unroll
            for (int i = 0; i < NP*4; i++) acc[i] = 0ull;
            const float* hq = hw + q*8;
            const float* r3base = sR3T + lane*KP;
#pragma unroll 2
            for (int k4 = 0; k4 < 16; k4++) {
                ulonglong2 hA[4], hB[4];
#pragma unroll
                for (int kk = 0; kk < 4; kk++) {
                    hA[kk] = *(const ulonglong2*)(hq + (4*k4+kk)*32);
                    hB[kk] = *(const ulonglong2*)(hq + (4*k4+kk)*32 + 4);
                }
#pragma unroll
                for (int p = 0; p < NP; p++) {
                    float4 w4 = *(const float4*)(r3base + p*(CC*KP) + 4*k4);
                    float wv[4] = {w4.x, w4.y, w4.z, w4.w};
#pragma unroll
                    for (int kk = 0; kk < 4; kk++) {
                        u64 w2 = pack2(wv[kk], wv[kk]);
                        ffma2(acc[p*4+0], hA[kk].x, w2);
                        ffma2(acc[p*4+1], hA[kk].y, w2);
                        ffma2(acc[p*4+2], hB[kk].x, w2);
                        ffma2(acc[p*4+3], hB[kk].y, w2);
                    }
                }
            }

            // TP message + vec4 atomic scatter for 8 edges
#pragma unroll
            for (int pr = 0; pr < 4; pr++) {
                float2 w0p = unpk(acc[0*4+pr]);
                float2 w1p = unpk(acc[1*4+pr]);
#pragma unroll
                for (int hh = 0; hh < 2; hh++) {
                    int j = pr*2 + hh;
                    float w0 = hh ? w0p.y : w0p.x;
                    float w1 = hh ? w1p.y : w1p.x;
                    float y0 = yx[j], y1 = yy[j], y2 = yz[j];
                    float ms, m0, m1, m2;
                    if (NP == 2) {
                        // layer 0: ss from species table in smem (exact same value)
                        float ss = sSU0[zs8[j]*CC + lane];
                        ms = w0*ss;
                        float w1s = w1*ss;
                        m0 = w1s*y0; m1 = w1s*y1; m2 = w1s*y2;
                    } else {
                        float2 w2p = unpk(acc[2*4+pr]);
                        float2 w3p = unpk(acc[3*4+pr]);
                        float2 w4p = unpk(acc[4*4+pr]);
                        float w2v = hh ? w2p.y : w2p.x;
                        float w3  = hh ? w3p.y : w3p.x;
                        float w4  = hh ? w4p.y : w4p.x;
                        float ss = uv8[j].x;
                        float v0 = uv8[j].y, v1 = uv8[j].z, v2 = uv8[j].w;
                        float dot = v0*y0 + v1*y1 + v2*y2;
                        float c0 = v1*y2 - v2*y1;
                        float c1 = v2*y0 - v0*y2;
                        float c2 = v0*y1 - v1*y0;
                        ms = w0*ss + w3*dot;
                        m0 = w1*ss*y0 + w2v*v0 + w4*c0;
                        m1 = w1*ss*y1 + w2v*v1 + w4*c1;
                        m2 = w1*ss*y2 + w2v*v2 + w4*c2;
                    }
                    red_v4(g_acc + d8[j]*CC + lane, ms, m0, m1, m2);
                }
            }
        }
        __syncwarp();
    }
}

// ---------------- node update: out linears, skip, product block --------------
// FUSE: additionally compute next layer's up-projection (su,vu) and zero acc.
#define NWB 16
template<bool FUSE>
__global__ void k_nodeupd(const float* __restrict__ Wouts,
                          const float* __restrict__ Woutv,
                          const float* __restrict__ Wscs,
                          const float* __restrict__ Wscv,
                          const float* __restrict__ Wp,
                          const float* __restrict__ Wlins,
                          const float* __restrict__ Wlinv,
                          const float* __restrict__ WusN,
                          const float* __restrict__ WuvN,
                          float* __restrict__ out, int l) {
    __shared__ float sWos[CC*CC], sWov[CC*CC], sWls[CC*CC], sWlv[CC*CC];
    __shared__ float sWus[CC*CC], sWuv[CC*CC];
    __shared__ float st[NWB][256];
    int tid = threadIdx.x;
    for (int i = tid; i < CC*CC; i += blockDim.x) {
        sWos[i] = Wouts[i]; sWov[i] = Woutv[i];
        sWls[i] = Wlins[i]; sWlv[i] = Wlinv[i];
        if (FUSE) { sWus[i] = WusN[i]; sWuv[i] = WuvN[i]; }
    }
    __syncthreads();
    int warp = tid >> 5, lane = tid & 31;
    int n = blockIdx.x * NWB + warp;
    if (n >= NN) return;

    float* xs = st[warp];
    float* xv = xs + 32;
    float* ys = xv + 96;
    float* yv = ys + 32;

    int z = g_z[n];
    float4 a4 = g_acc[n*CC + lane];
    float4 o4 = g_sv [n*CC + lane];
    xs[lane]       = a4.x * INV_AVG;
    xv[lane*3 + 0] = a4.y * INV_AVG;
    xv[lane*3 + 1] = a4.z * INV_AVG;
    xv[lane*3 + 2] = a4.w * INV_AVG;
    ys[lane]       = o4.x;
    yv[lane*3 + 0] = o4.y;
    yv[lane*3 + 1] = o4.z;
    yv[lane*3 + 2] = o4.w;
    __syncwarp();

    const float* Ws = Wscs + z*CC*CC;
    const float* Wv = Wscv + z*CC*CC;
    float s2 = 0.f, v20 = 0.f, v21 = 0.f, v22 = 0.f;
    float scs = 0.f, sv0 = 0.f, sv1 = 0.f, sv2 = 0.f;
#pragma unroll
    for (int k = 0; k < CC; k++) {
        float wo = sWos[k*CC + lane], wvv = sWov[k*CC + lane];
        s2  += xs[k]     * wo;
        v20 += xv[k*3+0] * wvv;
        v21 += xv[k*3+1] * wvv;
        v22 += xv[k*3+2] * wvv;
        float as = __ldg(Ws + k*CC + lane), av = __ldg(Wv + k*CC + lane);
        scs += ys[k]     * as;
        sv0 += yv[k*3+0] * av;
        sv1 += yv[k*3+1] * av;
        sv2 += yv[k*3+2] * av;
    }

    float we0 = __ldg(Wp + (z*5+0)*CC + lane);
    float we1 = __ldg(Wp + (z*5+1)*CC + lane);
    float we2 = __ldg(Wp + (z*5+2)*CC + lane);
    float we3 = __ldg(Wp + (z*5+3)*CC + lane);
    float we4 = __ldg(Wp + (z*5+4)*CC + lane);

    float vdot = v20*v20 + v21*v21 + v22*v22;
    float ps  = we0*s2 + we1*s2*s2 + we2*vdot;
    float pv0 = we3*v20 + we4*s2*v20;
    float pv1 = we3*v21 + we4*s2*v21;
    float pv2 = we3*v22 + we4*s2*v22;
    __syncwarp();
    xs[lane] = ps;
    xv[lane*3+0] = pv0; xv[lane*3+1] = pv1; xv[lane*3+2] = pv2;
    __syncwarp();

    float sn = scs, vn0 = sv0, vn1 = sv1, vn2 = sv2;
#pragma unroll
    for (int k = 0; k < CC; k++) {
        float wl = sWls[k*CC + lane], wlv = sWlv[k*CC + lane];
        sn  += xs[k]     * wl;
        vn0 += xv[k*3+0] * wlv;
        vn1 += xv[k*3+1] * wlv;
        vn2 += xv[k*3+2] * wlv;
    }
    g_sv[n*CC + lane] = make_float4(sn, vn0, vn1, vn2);
    out[n*(LL*CC) + l*CC + lane] = sn;

    if (FUSE) {
        // next layer's up-projection from fresh (sn, vn) + zero accumulators
        __syncwarp();
        ys[lane]       = sn;
        yv[lane*3 + 0] = vn0;
        yv[lane*3 + 1] = vn1;
        yv[lane*3 + 2] = vn2;
        __syncwarp();
        float a = 0.f, u0 = 0.f, u1 = 0.f, u2 = 0.f;
#pragma unroll
        for (int k = 0; k < CC; k++) {
            float ws = sWus[k*CC + lane], wv = sWuv[k*CC + lane];
            a  += ys[k]     * ws;
            u0 += yv[k*3+0] * wv;
            u1 += yv[k*3+1] * wv;
            u2 += yv[k*3+2] * wv;
        }
        g_up [n*CC + lane] = make_float4(a, u0, u1, u2);
        g_acc[n*CC + lane] = make_float4(0.f, 0.f, 0.f, 0.f);
    }
}

// ---------------- launch ------------------------------------------------------
extern "C" void kernel_launch(void* const* d_in, const int* in_sizes, int n_in,
                              void* d_out, int out_size) {
    const float* pos     = (const float*)d_in[0];
    const float* attrs   = (const float*)d_in[1];
    const float* shifts  = (const float*)d_in[2];
    const float* W_embed = (const float*)d_in[3];
    const float* W_up_s  = (const float*)d_in[4];
    const float* W_up_v  = (const float*)d_in[5];
    const float* R1      = (const float*)d_in[6];
    const float* R2      = (const float*)d_in[7];
    const float* R3      = (const float*)d_in[8];
    const float* W_out_s = (const float*)d_in[9];
    const float* W_out_v = (const float*)d_in[10];
    const float* Wsc_s   = (const float*)d_in[11];
    const float* Wsc_v   = (const float*)d_in[12];
    const float* Wp      = (const float*)d_in[13];
    const float* W_lin_s = (const float*)d_in[14];
    const float* W_lin_v = (const float*)d_in[15];
    const int*   ei      = (const int*)d_in[16];
    const int* src = ei;
    const int* dst = ei + EE;
    float* out = (float*)d_out;

    int smem = (NB*HH + HH*HH + 5*CC*KP + EW*HWF + ZZ*CC) * (int)sizeof(float); // 112384 B
    cudaFuncSetAttribute(k_edge<2>, cudaFuncAttributeMaxDynamicSharedMemorySize, smem);
    cudaFuncSetAttribute(k_edge<5>, cudaFuncAttributeMaxDynamicSharedMemorySize, smem);

    k_zidx <<<(NN + 255)/256, 256>>>(attrs);
    k_pre0 <<<1, ZZ*32>>>(W_embed, W_up_s);
    k_init0<<<(NN*CC + 255)/256, 256>>>(W_embed);
    k_geom <<<(EE + 255)/256, 256>>>(pos, shifts, src, dst);

    // layer 0 (v == 0 → 2-path edge kernel, ss from species table;
    //          nodeupd fuses layer-1 up-proj + acc zeroing)
    k_edge<2><<<296, ETPB, smem>>>(R1, R2, R3);
    k_nodeupd<true><<<(NN + NWB - 1)/NWB, NWB*32>>>(
        W_out_s, W_out_v, Wsc_s, Wsc_v, Wp, W_lin_s, W_lin_v,
        W_up_s + CC*CC, W_up_v + CC*CC, out, 0);

    // layer 1 (full 5-path edge kernel)
    k_edge<5><<<296, ETPB, smem>>>(R1 + NB*HH, R2 + HH*HH, R3 + HH*5*CC);
    k_nodeupd<false><<<(NN + NWB - 1)/NWB, NWB*32>>>(
        W_out_s + CC*CC, W_out_v + CC*CC,
        Wsc_s + ZZ*CC*CC, Wsc_v + ZZ*CC*CC, Wp + ZZ*5*CC,
        W_lin_s + CC*CC, W_lin_v + CC*CC,
        W_up_s, W_up_v, out, 1);
}

// round 12
// speedup vs baseline: 1.4203x; 1.0052x over previous
#include <cuda_runtime.h>
#include <math.h>

#define NN 50000
#define EE 800000
#define CC 32
#define ZZ 10
#define LL 2
#define NB 8
#define HH 64
#define INV_AVG (1.0f/16.0f)
#define RCUT_INV (1.0f/5.0f)

typedef unsigned long long u64;

// ---------------- scratch (static device globals; no allocation) -------------
__device__ float4 g_sv [NN*CC];   // {s, v0, v1, v2}
__device__ float4 g_up [NN*CC];   // {su, vu0, vu1, vu2}
__device__ float4 g_acc[NN*CC];   // {S, V0, V1, V2}
__device__ float4 g_Y1 [EE];      // {y0, y1, y2, pad}
__device__ float  g_ef [EE*NB];
__device__ int2   g_edge [EE];    // {src, dst}   (layer >= 1)
__device__ int2   g_edge0[EE];    // {z[src], dst} (layer 0)
__device__ int    g_z  [NN];
__device__ float  g_su0[ZZ*CC];   // layer-0 su table (species-only)

// ---------------- packed fp32x2 helpers (SASS FFMA2 via PTX) -----------------
__device__ __forceinline__ u64 pack2(float lo, float hi) {
    u64 r; asm("mov.b64 %0, {%1,%2};" : "=l"(r) : "f"(lo), "f"(hi)); return r;
}
__device__ __forceinline__ float2 unpk(u64 v) {
    float2 f; asm("mov.b64 {%0,%1}, %2;" : "=f"(f.x), "=f"(f.y) : "l"(v)); return f;
}
__device__ __forceinline__ void ffma2(u64 &d, u64 a, u64 b) {
    asm("fma.rn.f32x2 %0, %1, %2, %0;" : "+l"(d) : "l"(a), "l"(b));
}
__device__ __forceinline__ float silu(float x) {
    return __fdividef(x, 1.0f + __expf(-x));
}
__device__ __forceinline__ void red_v4(float4* p, float a, float b, float c, float d) {
    asm volatile("red.global.add.v4.f32 [%0], {%1,%2,%3,%4};"
                 :: "l"(p), "f"(a), "f"(b), "f"(c), "f"(d) : "memory");
}

// ---------------- species index from one-hot ---------------------------------
__global__ void k_zidx(const float* __restrict__ attrs) {
    int n = blockIdx.x * blockDim.x + threadIdx.x;
    if (n >= NN) return;
    int z = 0;
#pragma unroll
    for (int j = 0; j < ZZ; j++)
        if (attrs[n*ZZ + j] > 0.5f) z = j;
    g_z[n] = z;
}

// ---------------- layer-0 su table: su0[z] = W_embed[z] @ W_up_s[0] ----------
__global__ void k_pre0(const float* __restrict__ W_embed,
                       const float* __restrict__ Wus) {
    int z = threadIdx.x >> 5, lane = threadIdx.x & 31;
    if (z >= ZZ) return;
    float a = 0.f;
#pragma unroll
    for (int k = 0; k < CC; k++)
        a += W_embed[z*CC + k] * Wus[k*CC + lane];
    g_su0[z*CC + lane] = a;
}

// ---------------- fused init: s=embed, v=0, up from table, acc=0 -------------
__global__ void k_init0(const float* __restrict__ W_embed) {
    int idx = blockIdx.x * blockDim.x + threadIdx.x;
    if (idx >= NN*CC) return;
    int n = idx >> 5, c = idx & 31;
    int z = g_z[n];
    g_sv [idx] = make_float4(W_embed[z*CC + c], 0.f, 0.f, 0.f);
    g_up [idx] = make_float4(g_su0[z*CC + c],   0.f, 0.f, 0.f);
    g_acc[idx] = make_float4(0.f, 0.f, 0.f, 0.f);
}

// ---------------- edge geometry: Y1 + radial features + packed indices -------
// NOTE: precise sinf per basis fn — fast-math trig here fails the 1e-3 gate.
__global__ void k_geom(const float* __restrict__ pos,
                       const float* __restrict__ shifts,
                       const int* __restrict__ src,
                       const int* __restrict__ dst) {
    int e = blockIdx.x * blockDim.x + threadIdx.x;
    if (e >= EE) return;
    int si = src[e], di = dst[e];
    g_edge [e] = make_int2(si, di);
    g_edge0[e] = make_int2(__ldg(g_z + si), di);   // layer-0 uses species of src
    float vx = pos[di*3+0] - pos[si*3+0] + shifts[e*3+0];
    float vy = pos[di*3+1] - pos[si*3+1] + shifts[e*3+1];
    float vz = pos[di*3+2] - pos[si*3+2] + shifts[e*3+2];
    float r  = sqrtf(vx*vx + vy*vy + vz*vz);
    float rs = fmaxf(r, 1e-9f);
    float inv = 1.0f / rs;
    g_Y1[e] = make_float4(vx*inv, vy*inv, vz*inv, 0.f);
    float x = r * RCUT_INV;
    float fc = 0.f;
    if (x < 1.0f) {
        float x2 = x*x, x3 = x2*x;
        float x6 = x3*x3, x7 = x6*x, x8 = x7*x;
        fc = 1.0f - 28.0f*x6 + 48.0f*x7 - 21.0f*x8;   // P=6 polynomial cutoff
    }
    float coef = 0.6324555320336759f * fc * inv;       // sqrt(2/RCUT)*fc/rs
    float arg0 = rs * (float)M_PI * RCUT_INV;
#pragma unroll
    for (int nb = 0; nb < NB; nb++)
        g_ef[e*NB + nb] = coef * sinf((float)(nb+1) * arg0);
}

// ---------------- fused edge kernel ------------------------------------------
// Phase A (lane = edge): radial MLP stages 1-2, FFMA2 packed, broadcast LDS.128
//   weights; silu'd hidden written transposed to per-warp smem.
// Phase B (lane = channel): stage-3 over 4 sub-batches of 8 edges (PROVEN
//   tiling). NP=2 (layer 0): v==0 → paths 2,3,4 exactly zero, ss from the
//   10x32 su0 smem table; only 2 R3T planes stored → smem small enough for
//   EW=8 (16 warps/SM). NP=5 (layer 1): proven EW=6 config.
#define HWF 2048          // 64*32 floats per warp
#define KP 68             // padded k stride (272B, 16B-aligned)

template<int NP, int EWW>
__global__ void __launch_bounds__(EWW*32, 2)
k_edge(const float* __restrict__ R1,
       const float* __restrict__ R2,
       const float* __restrict__ R3) {
    const int NT = EWW*32;
    extern __shared__ float smf[];
    float* sR1  = smf;                      // 512
    float* sR2  = sR1 + NB*HH;              // 4096
    float* sR3T = sR2 + HH*HH;              // NP*32*68
    float* hall = sR3T + NP*CC*KP;          // EWW*2048
    float* sSU0 = hall + EWW*HWF;           // ZZ*CC (layer 0 only)
    int tid = threadIdx.x;
    for (int i = tid; i < NB*HH;    i += NT) sR1[i] = R1[i];
    for (int i = tid; i < HH*HH;    i += NT) sR2[i] = R2[i];
    for (int i = tid; i < NP*CC*HH; i += NT) {
        int k = i & 63, rest = i >> 6;
        int c = rest & 31, p = rest >> 5;
        sR3T[p*(CC*KP) + c*KP + k] = R3[k*5*CC + p*CC + c];
    }
    if (NP == 2)
        for (int i = tid; i < ZZ*CC; i += NT) sSU0[i] = g_su0[i];
    __syncthreads();

    int warp = tid >> 5, lane = tid & 31;
    float* hw = hall + warp*HWF;
    const int nbatch = EE/32;   // 25000, exact

    for (int b = blockIdx.x*EWW + warp; b < nbatch; b += gridDim.x*EWW) {
        int ebase = b*32;
        int e = ebase + lane;

        // ======== phase A: lane = edge ========
        float4 efa = *(const float4*)&g_ef[e*NB];
        float4 efb = *(const float4*)&g_ef[e*NB + 4];
        float ef[8] = {efa.x, efa.y, efa.z, efa.w, efb.x, efb.y, efb.z, efb.w};

        // stage 1: [8] -> [64]
        u64 h2[32];
#pragma unroll
        for (int m = 0; m < 32; m++) h2[m] = 0ull;
#pragma unroll
        for (int k = 0; k < 8; k++) {
            u64 a = pack2(ef[k], ef[k]);
            const ulonglong2* row = (const ulonglong2*)(sR1 + k*HH);
#pragma unroll
            for (int m = 0; m < 16; m++) {
                ulonglong2 w = row[m];
                ffma2(h2[2*m],   a, w.x);
                ffma2(h2[2*m+1], a, w.y);
            }
        }
#pragma unroll
        for (int m = 0; m < 32; m++) {
            float2 f = unpk(h2[m]);
            h2[m] = pack2(silu(f.x), silu(f.y));
        }

        // stage 2: [64] -> [64], split into two output halves (reg pressure)
#pragma unroll
        for (int Hh = 0; Hh < 2; Hh++) {
            u64 acc[16];
#pragma unroll
            for (int m = 0; m < 16; m++) acc[m] = 0ull;
#pragma unroll 4
            for (int kk = 0; kk < 32; kk++) {
                float2 hk = unpk(h2[kk]);
                u64 a0 = pack2(hk.x, hk.x);
                u64 a1 = pack2(hk.y, hk.y);
                const ulonglong2* r0 = (const ulonglong2*)(sR2 + (2*kk)*HH   + Hh*32);
                const ulonglong2* r1 = (const ulonglong2*)(sR2 + (2*kk+1)*HH + Hh*32);
#pragma unroll
                for (int m = 0; m < 8; m++) {
                    ulonglong2 w0 = r0[m], w1 = r1[m];
                    ffma2(acc[2*m],   a0, w0.x);
                    ffma2(acc[2*m+1], a0, w0.y);
                    ffma2(acc[2*m],   a1, w1.x);
                    ffma2(acc[2*m+1], a1, w1.y);
                }
            }
#pragma unroll
            for (int m = 0; m < 16; m++) {
                float2 f = unpk(acc[m]);
                hw[(Hh*32 + 2*m)*32   + lane] = silu(f.x);
                hw[(Hh*32 + 2*m+1)*32 + lane] = silu(f.y);
            }
        }
        __syncwarp();

        // ======== phase B: lane = channel, 4 sub-batches of 8 edges ========
#pragma unroll 1
        for (int q = 0; q < 4; q++) {
            // hoisted gathers (overlap with k-loop)
            int eg0 = ebase + q*8;
            float4 uv8[8];
            int    zs8[8];
            float  yx[8], yy[8], yz[8];
            int    d8[8];
#pragma unroll
            for (int j = 0; j < 8; j++) {
                int2 sd = __ldg((NP == 2 ? g_edge0 : g_edge) + eg0 + j);
                d8[j] = sd.y;
                float4 y4 = __ldg(g_Y1 + eg0 + j);
                yx[j] = y4.x; yy[j] = y4.y; yz[j] = y4.z;
                if (NP == 2) zs8[j] = sd.x;
                else         uv8[j] = __ldg(g_up + sd.x*CC + lane);
            }

            u64 acc[NP*4];   // [p][pair]
#pragma unroll
            for (int i = 0; i < NP*4; i++) acc[i] = 0ull;
            const float* hq = hw + q*8;
            const float* r3base = sR3T + lane*KP;
#pragma unroll 2
            for (int k4 = 0; k4 < 16; k4++) {
                ulonglong2 hA[4], hB[4];
#pragma unroll
                for (int kk = 0; kk < 4; kk++) {
                    hA[kk] = *(const ulonglong2*)(hq + (4*k4+kk)*32);
                    hB[kk] = *(const ulonglong2*)(hq + (4*k4+kk)*32 + 4);
                }
#pragma unroll
                for (int p = 0; p < NP; p++) {
                    float4 w4 = *(const float4*)(r3base + p*(CC*KP) + 4*k4);
                    float wv[4] = {w4.x, w4.y, w4.z, w4.w};
#pragma unroll
                    for (int kk = 0; kk < 4; kk++) {
                        u64 w2 = pack2(wv[kk], wv[kk]);
                        ffma2(acc[p*4+0], hA[kk].x, w2);
                        ffma2(acc[p*4+1], hA[kk].y, w2);
                        ffma2(acc[p*4+2], hB[kk].x, w2);
                        ffma2(acc[p*4+3], hB[kk].y, w2);
                    }
                }
            }

            // TP message + vec4 atomic scatter for 8 edges
#pragma unroll
            for (int pr = 0; pr < 4; pr++) {
                float2 w0p = unpk(acc[0*4+pr]);
                float2 w1p = unpk(acc[1*4+pr]);
#pragma unroll
                for (int hh = 0; hh < 2; hh++) {
                    int j = pr*2 + hh;
                    float w0 = hh ? w0p.y : w0p.x;
                    float w1 = hh ? w1p.y : w1p.x;
                    float y0 = yx[j], y1 = yy[j], y2 = yz[j];
                    float ms, m0, m1, m2;
                    if (NP == 2) {
                        // layer 0: ss from species table in smem (exact same value)
                        float ss = sSU0[zs8[j]*CC + lane];
                        ms = w0*ss;
                        float w1s = w1*ss;
                        m0 = w1s*y0; m1 = w1s*y1; m2 = w1s*y2;
                    } else {
                        float2 w2p = unpk(acc[2*4+pr]);
                        float2 w3p = unpk(acc[3*4+pr]);
                        float2 w4p = unpk(acc[4*4+pr]);
                        float w2v = hh ? w2p.y : w2p.x;
                        float w3  = hh ? w3p.y : w3p.x;
                        float w4  = hh ? w4p.y : w4p.x;
                        float ss = uv8[j].x;
                        float v0 = uv8[j].y, v1 = uv8[j].z, v2 = uv8[j].w;
                        float dot = v0*y0 + v1*y1 + v2*y2;
                        float c0 = v1*y2 - v2*y1;
                        float c1 = v2*y0 - v0*y2;
                        float c2 = v0*y1 - v1*y0;
                        ms = w0*ss + w3*dot;
                        m0 = w1*ss*y0 + w2v*v0 + w4*c0;
                        m1 = w1*ss*y1 + w2v*v1 + w4*c1;
                        m2 = w1*ss*y2 + w2v*v2 + w4*c2;
                    }
                    red_v4(g_acc + d8[j]*CC + lane, ms, m0, m1, m2);
                }
            }
        }
        __syncwarp();
    }
}

// ---------------- node update: out linears, skip, product block --------------
// FUSE: additionally compute next layer's up-projection (su,vu) and zero acc.
#define NWB 16
template<bool FUSE>
__global__ void k_nodeupd(const float* __restrict__ Wouts,
                          const float* __restrict__ Woutv,
                          const float* __restrict__ Wscs,
                          const float* __restrict__ Wscv,
                          const float* __restrict__ Wp,
                          const float* __restrict__ Wlins,
                          const float* __restrict__ Wlinv,
                          const float* __restrict__ WusN,
                          const float* __restrict__ WuvN,
                          float* __restrict__ out, int l) {
    __shared__ float sWos[CC*CC], sWov[CC*CC], sWls[CC*CC], sWlv[CC*CC];
    __shared__ float sWus[CC*CC], sWuv[CC*CC];
    __shared__ float st[NWB][256];
    int tid = threadIdx.x;
    for (int i = tid; i < CC*CC; i += blockDim.x) {
        sWos[i] = Wouts[i]; sWov[i] = Woutv[i];
        sWls[i] = Wlins[i]; sWlv[i] = Wlinv[i];
        if (FUSE) { sWus[i] = WusN[i]; sWuv[i] = WuvN[i]; }
    }
    __syncthreads();
    int warp = tid >> 5, lane = tid & 31;
    int n = blockIdx.x * NWB + warp;
    if (n >= NN) return;

    float* xs = st[warp];
    float* xv = xs + 32;
    float* ys = xv + 96;
    float* yv = ys + 32;

    int z = g_z[n];
    float4 a4 = g_acc[n*CC + lane];
    float4 o4 = g_sv [n*CC + lane];
    xs[lane]       = a4.x * INV_AVG;
    xv[lane*3 + 0] = a4.y * INV_AVG;
    xv[lane*3 + 1] = a4.z * INV_AVG;
    xv[lane*3 + 2] = a4.w * INV_AVG;
    ys[lane]       = o4.x;
    yv[lane*3 + 0] = o4.y;
    yv[lane*3 + 1] = o4.z;
    yv[lane*3 + 2] = o4.w;
    __syncwarp();

    const float* Ws = Wscs + z*CC*CC;
    const float* Wv = Wscv + z*CC*CC;
    float s2 = 0.f, v20 = 0.f, v21 = 0.f, v22 = 0.f;
    float scs = 0.f, sv0 = 0.f, sv1 = 0.f, sv2 = 0.f;
#pragma unroll
    for (int k = 0; k < CC; k++) {
        float wo = sWos[k*CC + lane], wvv = sWov[k*CC + lane];
        s2  += xs[k]     * wo;
        v20 += xv[k*3+0] * wvv;
        v21 += xv[k*3+1] * wvv;
        v22 += xv[k*3+2] * wvv;
        float as = __ldg(Ws + k*CC + lane), av = __ldg(Wv + k*CC + lane);
        scs += ys[k]     * as;
        sv0 += yv[k*3+0] * av;
        sv1 += yv[k*3+1] * av;
        sv2 += yv[k*3+2] * av;
    }

    float we0 = __ldg(Wp + (z*5+0)*CC + lane);
    float we1 = __ldg(Wp + (z*5+1)*CC + lane);
    float we2 = __ldg(Wp + (z*5+2)*CC + lane);
    float we3 = __ldg(Wp + (z*5+3)*CC + lane);
    float we4 = __ldg(Wp + (z*5+4)*CC + lane);

    float vdot = v20*v20 + v21*v21 + v22*v22;
    float ps  = we0*s2 + we1*s2*s2 + we2*vdot;
    float pv0 = we3*v20 + we4*s2*v20;
    float pv1 = we3*v21 + we4*s2*v21;
    float pv2 = we3*v22 + we4*s2*v22;
    __syncwarp();
    xs[lane] = ps;
    xv[lane*3+0] = pv0; xv[lane*3+1] = pv1; xv[lane*3+2] = pv2;
    __syncwarp();

    float sn = scs, vn0 = sv0, vn1 = sv1, vn2 = sv2;
#pragma unroll
    for (int k = 0; k < CC; k++) {
        float wl = sWls[k*CC + lane], wlv = sWlv[k*CC + lane];
        sn  += xs[k]     * wl;
        vn0 += xv[k*3+0] * wlv;
        vn1 += xv[k*3+1] * wlv;
        vn2 += xv[k*3+2] * wlv;
    }
    g_sv[n*CC + lane] = make_float4(sn, vn0, vn1, vn2);
    out[n*(LL*CC) + l*CC + lane] = sn;

    if (FUSE) {
        // next layer's up-projection from fresh (sn, vn) + zero accumulators
        __syncwarp();
        ys[lane]       = sn;
        yv[lane*3 + 0] = vn0;
        yv[lane*3 + 1] = vn1;
        yv[lane*3 + 2] = vn2;
        __syncwarp();
        float a = 0.f, u0 = 0.f, u1 = 0.f, u2 = 0.f;
#pragma unroll
        for (int k = 0; k < CC; k++) {
            float ws = sWus[k*CC + lane], wv = sWuv[k*CC + lane];
            a  += ys[k]     * ws;
            u0 += yv[k*3+0] * wv;
            u1 += yv[k*3+1] * wv;
            u2 += yv[k*3+2] * wv;
        }
        g_up [n*CC + lane] = make_float4(a, u0, u1, u2);
        g_acc[n*CC + lane] = make_float4(0.f, 0.f, 0.f, 0.f);
    }
}

// ---------------- launch ------------------------------------------------------
extern "C" void kernel_launch(void* const* d_in, const int* in_sizes, int n_in,
                              void* d_out, int out_size) {
    const float* pos     = (const float*)d_in[0];
    const float* attrs   = (const float*)d_in[1];
    const float* shifts  = (const float*)d_in[2];
    const float* W_embed = (const float*)d_in[3];
    const float* W_up_s  = (const float*)d_in[4];
    const float* W_up_v  = (const float*)d_in[5];
    const float* R1      = (const float*)d_in[6];
    const float* R2      = (const float*)d_in[7];
    const float* R3      = (const float*)d_in[8];
    const float* W_out_s = (const float*)d_in[9];
    const float* W_out_v = (const float*)d_in[10];
    const float* Wsc_s   = (const float*)d_in[11];
    const float* Wsc_v   = (const float*)d_in[12];
    const float* Wp      = (const float*)d_in[13];
    const float* W_lin_s = (const float*)d_in[14];
    const float* W_lin_v = (const float*)d_in[15];
    const int*   ei      = (const int*)d_in[16];
    const int* src = ei;
    const int* dst = ei + EE;
    float* out = (float*)d_out;

    // L0 (NP=2, EW=8): 512 + 4096 + 2*32*68 + 8*2048 + 320 = 25664 floats = 102656 B
    int smem0 = (NB*HH + HH*HH + 2*CC*KP + 8*HWF + ZZ*CC) * (int)sizeof(float);
    // L1 (NP=5, EW=6): 512 + 4096 + 5*32*68 + 6*2048 = 27776 floats = 111104 B
    int smem1 = (NB*HH + HH*HH + 5*CC*KP + 6*HWF) * (int)sizeof(float);
    cudaFuncSetAttribute((const void*)k_edge<2,8>, cudaFuncAttributeMaxDynamicSharedMemorySize, smem0);
    cudaFuncSetAttribute((const void*)k_edge<5,6>, cudaFuncAttributeMaxDynamicSharedMemorySize, smem1);

    k_zidx <<<(NN + 255)/256, 256>>>(attrs);
    k_pre0 <<<1, ZZ*32>>>(W_embed, W_up_s);
    k_init0<<<(NN*CC + 255)/256, 256>>>(W_embed);
    k_geom <<<(EE + 255)/256, 256>>>(pos, shifts, src, dst);

    // layer 0 (v == 0 → 2-path edge kernel, ss from species table, 8 warps/blk;
    //          nodeupd fuses layer-1 up-proj + acc zeroing)
    k_edge<2,8><<<296, 8*32, smem0>>>(R1, R2, R3);
    k_nodeupd<true><<<(NN + NWB - 1)/NWB, NWB*32>>>(
        W_out_s, W_out_v, Wsc_s, Wsc_v, Wp, W_lin_s, W_lin_v,
        W_up_s + CC*CC, W_up_v + CC*CC, out, 0);

    // layer 1 (full 5-path edge kernel, proven 6-warp config)
    k_edge<5,6><<<296, 6*32, smem1>>>(R1 + NB*HH, R2 + HH*HH, R3 + HH*5*CC);
    k_nodeupd<false><<<(NN + NWB - 1)/NWB, NWB*32>>>(
        W_out_s + CC*CC, W_out_v + CC*CC,
        Wsc_s + ZZ*CC*CC, Wsc_v + ZZ*CC*CC, Wp + ZZ*5*CC,
        W_lin_s + CC*CC, W_lin_v + CC*CC,
        W_up_s, W_up_v, out, 1);
}

// round 13
// speedup vs baseline: 3.7770x; 2.6593x over previous
#include <cuda_runtime.h>
#include <math.h>

#define NN 50000
#define EE 800000
#define CC 32
#define ZZ 10
#define LL 2
#define NB 8
#define HH 64
#define TT 8192
#define INV_AVG (1.0f/16.0f)
#define RCUT_INV (1.0f/5.0f)

// ---------------- scratch (static device globals; no allocation) -------------
__device__ float4 g_sv [NN*CC];   // {s, v0, v1, v2}
__device__ float4 g_up [NN*CC];   // {su, vu0, vu1, vu2}
__device__ float4 g_acc[NN*CC];   // {S, V0, V1, V2}
__device__ float4 g_Y1 [EE];      // {y0, y1, y2, pad}
__device__ float  g_tc [EE];      // table coordinate (r mapped to [0, TT-1])
__device__ int2   g_edge [EE];    // {src, dst}   (layer >= 1)
__device__ int2   g_edge0[EE];    // {z[src], dst} (layer 0)
__device__ int    g_z  [NN];
__device__ float  g_su0[ZZ*CC];   // layer-0 su table (species-only)
__device__ float  g_wtab[LL*TT*5*CC];  // radial-MLP output table per layer

__device__ __forceinline__ float silu(float x) {
    return __fdividef(x, 1.0f + __expf(-x));
}
__device__ __forceinline__ void red_v4(float4* p, float a, float b, float c, float d) {
    asm volatile("red.global.add.v4.f32 [%0], {%1,%2,%3,%4};"
                 :: "l"(p), "f"(a), "f"(b), "f"(c), "f"(d) : "memory");
}

// ---------------- species index from one-hot ---------------------------------
__global__ void k_zidx(const float* __restrict__ attrs) {
    int n = blockIdx.x * blockDim.x + threadIdx.x;
    if (n >= NN) return;
    int z = 0;
#pragma unroll
    for (int j = 0; j < ZZ; j++)
        if (attrs[n*ZZ + j] > 0.5f) z = j;
    g_z[n] = z;
}

// ---------------- layer-0 su table: su0[z] = W_embed[z] @ W_up_s[0] ----------
__global__ void k_pre0(const float* __restrict__ W_embed,
                       const float* __restrict__ Wus) {
    int z = threadIdx.x >> 5, lane = threadIdx.x & 31;
    if (z >= ZZ) return;
    float a = 0.f;
#pragma unroll
    for (int k = 0; k < CC; k++)
        a += W_embed[z*CC + k] * Wus[k*CC + lane];
    g_su0[z*CC + lane] = a;
}

// ---------------- fused init: s=embed, v=0, up from table, acc=0 -------------
__global__ void k_init0(const float* __restrict__ W_embed) {
    int idx = blockIdx.x * blockDim.x + threadIdx.x;
    if (idx >= NN*CC) return;
    int n = idx >> 5, c = idx & 31;
    int z = g_z[n];
    g_sv [idx] = make_float4(W_embed[z*CC + c], 0.f, 0.f, 0.f);
    g_up [idx] = make_float4(g_su0[z*CC + c],   0.f, 0.f, 0.f);
    g_acc[idx] = make_float4(0.f, 0.f, 0.f, 0.f);
}

// ---------------- edge geometry: Y1 + table coord + packed indices -----------
__global__ void k_geom(const float* __restrict__ pos,
                       const float* __restrict__ shifts,
                       const int* __restrict__ src,
                       const int* __restrict__ dst) {
    int e = blockIdx.x * blockDim.x + threadIdx.x;
    if (e >= EE) return;
    int si = src[e], di = dst[e];
    g_edge [e] = make_int2(si, di);
    g_edge0[e] = make_int2(__ldg(g_z + si), di);   // layer-0 uses species of src
    float vx = pos[di*3+0] - pos[si*3+0] + shifts[e*3+0];
    float vy = pos[di*3+1] - pos[si*3+1] + shifts[e*3+1];
    float vz = pos[di*3+2] - pos[si*3+2] + shifts[e*3+2];
    float r  = sqrtf(vx*vx + vy*vy + vz*vz);
    float rs = fmaxf(r, 1e-9f);
    float inv = 1.0f / rs;
    g_Y1[e] = make_float4(vx*inv, vy*inv, vz*inv, 0.f);
    float x = r * RCUT_INV;
    g_tc[e] = fminf(x, 1.0f) * (float)(TT - 1);
}

// ---------------- radial-MLP table build --------------------------------------
// w(r) = R3^T silu(R2 silu(R1 · edge_feats(r))) is a smooth 1-D function; we
// evaluate it exactly (precise sinf, fp32 MLP) at TT uniform r-points.
// One warp per entry; lane = 2 hidden dims; shfl broadcasts for the 64-dim dot.
__global__ void k_table(const float* __restrict__ R1,
                        const float* __restrict__ R2,
                        const float* __restrict__ R3, int layer) {
    extern __shared__ float sm[];
    float* sR1 = sm;                 // 8*64
    float* sR2 = sR1 + NB*HH;        // 64*64
    float* sR3 = sR2 + HH*HH;        // 64*160
    int tid = threadIdx.x;
    for (int i = tid; i < NB*HH;   i += blockDim.x) sR1[i] = R1[i];
    for (int i = tid; i < HH*HH;   i += blockDim.x) sR2[i] = R2[i];
    for (int i = tid; i < HH*5*CC; i += blockDim.x) sR3[i] = R3[i];
    __syncthreads();

    int warp = tid >> 5, lane = tid & 31;
    int i = blockIdx.x * (blockDim.x >> 5) + warp;
    if (i >= TT) return;

    // exact edge_feats at r_i (matches reference formula; precise sinf)
    float r  = 5.0f * (float)i / (float)(TT - 1);
    float rs = fmaxf(r, 1e-9f);
    float inv = 1.0f / rs;
    float x = r * RCUT_INV;
    float fc = 0.f;
    if (x < 1.0f) {
        float x2 = x*x, x3 = x2*x;
        float x6 = x3*x3, x7 = x6*x, x8 = x7*x;
        fc = 1.0f - 28.0f*x6 + 48.0f*x7 - 21.0f*x8;
    }
    float coef = 0.6324555320336759f * fc * inv;
    float arg0 = rs * (float)M_PI * RCUT_INV;
    float ef[NB];
#pragma unroll
    for (int nb = 0; nb < NB; nb++)
        ef[nb] = coef * sinf((float)(nb+1) * arg0);

    // stage 1: [8] -> [64] (lane holds dims lane, lane+32)
    float h0 = 0.f, h1 = 0.f;
#pragma unroll
    for (int k = 0; k < NB; k++) {
        h0 += ef[k] * sR1[k*HH + lane];
        h1 += ef[k] * sR1[k*HH + lane + 32];
    }
    h0 = silu(h0); h1 = silu(h1);

    // stage 2: [64] -> [64]
    float a0 = 0.f, a1 = 0.f;
#pragma unroll
    for (int k = 0; k < 32; k++) {
        float va = __shfl_sync(0xffffffffu, h0, k);
        float vb = __shfl_sync(0xffffffffu, h1, k);
        a0 += va * sR2[k*HH + lane]        + vb * sR2[(k+32)*HH + lane];
        a1 += va * sR2[k*HH + lane + 32]   + vb * sR2[(k+32)*HH + lane + 32];
    }
    a0 = silu(a0); a1 = silu(a1);

    // stage 3: [64] -> [5,32]
    float w[5] = {0.f, 0.f, 0.f, 0.f, 0.f};
#pragma unroll
    for (int k = 0; k < 32; k++) {
        float va = __shfl_sync(0xffffffffu, a0, k);
        float vb = __shfl_sync(0xffffffffu, a1, k);
#pragma unroll
        for (int p = 0; p < 5; p++)
            w[p] += va * sR3[k*5*CC + p*CC + lane]
                  + vb * sR3[(k+32)*5*CC + p*CC + lane];
    }
    float* out = g_wtab + ((size_t)layer*TT + i) * (5*CC);
#pragma unroll
    for (int p = 0; p < 5; p++)
        out[p*CC + lane] = w[p];
}

// ---------------- edge kernel: table lookup + TP message + scatter -----------
// warp per edge (grid-stride); lane = channel. NP=2 (layer 0): v==0 so only
// paths 0,1 matter and ss comes from the species table in smem.
template<int NP>
__global__ void __launch_bounds__(256)
k_edge2(int layer) {
    __shared__ float sSU0[ZZ*CC];
    if (NP == 2) {
        for (int i = threadIdx.x; i < ZZ*CC; i += blockDim.x) sSU0[i] = g_su0[i];
        __syncthreads();
    }
    int gw   = (blockIdx.x * blockDim.x + threadIdx.x) >> 5;
    int nw   = (gridDim.x * blockDim.x) >> 5;
    int lane = threadIdx.x & 31;
    const float* tab = g_wtab + (size_t)layer*TT*(5*CC);
    constexpr int NW = (NP == 2) ? 2 : 5;

    for (int e = gw; e < EE; e += nw) {
        int2 sd = __ldg((NP == 2 ? g_edge0 : g_edge) + e);
        float tc = __ldg(g_tc + e);
        int i0 = min((int)tc, TT - 2);
        float f = tc - (float)i0;
        const float* rowA = tab + (size_t)i0 * (5*CC);
        float w[NW];
#pragma unroll
        for (int p = 0; p < NW; p++) {
            float a = __ldg(rowA + p*CC + lane);
            float b = __ldg(rowA + 5*CC + p*CC + lane);
            w[p] = fmaf(f, b - a, a);
        }
        float4 y4 = __ldg(g_Y1 + e);
        float y0 = y4.x, y1 = y4.y, y2 = y4.z;
        float ms, m0, m1, m2;
        if (NP == 2) {
            float ss = sSU0[sd.x*CC + lane];
            ms = w[0] * ss;
            float w1s = w[1] * ss;
            m0 = w1s*y0; m1 = w1s*y1; m2 = w1s*y2;
        } else {
            float4 uv = __ldg(g_up + sd.x*CC + lane);
            float ss = uv.x, v0 = uv.y, v1 = uv.z, v2 = uv.w;
            float dot = v0*y0 + v1*y1 + v2*y2;
            float c0 = v1*y2 - v2*y1;
            float c1 = v2*y0 - v0*y2;
            float c2 = v0*y1 - v1*y0;
            ms = w[0]*ss + w[3]*dot;
            m0 = w[1]*ss*y0 + w[2]*v0 + w[4]*c0;
            m1 = w[1]*ss*y1 + w[2]*v1 + w[4]*c1;
            m2 = w[1]*ss*y2 + w[2]*v2 + w[4]*c2;
        }
        red_v4(g_acc + sd.y*CC + lane, ms, m0, m1, m2);
    }
}

// ---------------- node update: out linears, skip, product block --------------
// FUSE: additionally compute next layer's up-projection (su,vu) and zero acc.
#define NWB 16
template<bool FUSE>
__global__ void k_nodeupd(const float* __restrict__ Wouts,
                          const float* __restrict__ Woutv,
                          const float* __restrict__ Wscs,
                          const float* __restrict__ Wscv,
                          const float* __restrict__ Wp,
                          const float* __restrict__ Wlins,
                          const float* __restrict__ Wlinv,
                          const float* __restrict__ WusN,
                          const float* __restrict__ WuvN,
                          float* __restrict__ out, int l) {
    __shared__ float sWos[CC*CC], sWov[CC*CC], sWls[CC*CC], sWlv[CC*CC];
    __shared__ float sWus[CC*CC], sWuv[CC*CC];
    __shared__ float st[NWB][256];
    int tid = threadIdx.x;
    for (int i = tid; i < CC*CC; i += blockDim.x) {
        sWos[i] = Wouts[i]; sWov[i] = Woutv[i];
        sWls[i] = Wlins[i]; sWlv[i] = Wlinv[i];
        if (FUSE) { sWus[i] = WusN[i]; sWuv[i] = WuvN[i]; }
    }
    __syncthreads();
    int warp = tid >> 5, lane = tid & 31;
    int n = blockIdx.x * NWB + warp;
    if (n >= NN) return;

    float* xs = st[warp];
    float* xv = xs + 32;
    float* ys = xv + 96;
    float* yv = ys + 32;

    int z = g_z[n];
    float4 a4 = g_acc[n*CC + lane];
    float4 o4 = g_sv [n*CC + lane];
    xs[lane]       = a4.x * INV_AVG;
    xv[lane*3 + 0] = a4.y * INV_AVG;
    xv[lane*3 + 1] = a4.z * INV_AVG;
    xv[lane*3 + 2] = a4.w * INV_AVG;
    ys[lane]       = o4.x;
    yv[lane*3 + 0] = o4.y;
    yv[lane*3 + 1] = o4.z;
    yv[lane*3 + 2] = o4.w;
    __syncwarp();

    const float* Ws = Wscs + z*CC*CC;
    const float* Wv = Wscv + z*CC*CC;
    float s2 = 0.f, v20 = 0.f, v21 = 0.f, v22 = 0.f;
    float scs = 0.f, sv0 = 0.f, sv1 = 0.f, sv2 = 0.f;
#pragma unroll
    for (int k = 0; k < CC; k++) {
        float wo = sWos[k*CC + lane], wvv = sWov[k*CC + lane];
        s2  += xs[k]     * wo;
        v20 += xv[k*3+0] * wvv;
        v21 += xv[k*3+1] * wvv;
        v22 += xv[k*3+2] * wvv;
        float as = __ldg(Ws + k*CC + lane), av = __ldg(Wv + k*CC + lane);
        scs += ys[k]     * as;
        sv0 += yv[k*3+0] * av;
        sv1 += yv[k*3+1] * av;
        sv2 += yv[k*3+2] * av;
    }

    float we0 = __ldg(Wp + (z*5+0)*CC + lane);
    float we1 = __ldg(Wp + (z*5+1)*CC + lane);
    float we2 = __ldg(Wp + (z*5+2)*CC + lane);
    float we3 = __ldg(Wp + (z*5+3)*CC + lane);
    float we4 = __ldg(Wp + (z*5+4)*CC + lane);

    float vdot = v20*v20 + v21*v21 + v22*v22;
    float ps  = we0*s2 + we1*s2*s2 + we2*vdot;
    float pv0 = we3*v20 + we4*s2*v20;
    float pv1 = we3*v21 + we4*s2*v21;
    float pv2 = we3*v22 + we4*s2*v22;
    __syncwarp();
    xs[lane] = ps;
    xv[lane*3+0] = pv0; xv[lane*3+1] = pv1; xv[lane*3+2] = pv2;
    __syncwarp();

    float sn = scs, vn0 = sv0, vn1 = sv1, vn2 = sv2;
#pragma unroll
    for (int k = 0; k < CC; k++) {
        float wl = sWls[k*CC + lane], wlv = sWlv[k*CC + lane];
        sn  += xs[k]     * wl;
        vn0 += xv[k*3+0] * wlv;
        vn1 += xv[k*3+1] * wlv;
        vn2 += xv[k*3+2] * wlv;
    }
    g_sv[n*CC + lane] = make_float4(sn, vn0, vn1, vn2);
    out[n*(LL*CC) + l*CC + lane] = sn;

    if (FUSE) {
        __syncwarp();
        ys[lane]       = sn;
        yv[lane*3 + 0] = vn0;
        yv[lane*3 + 1] = vn1;
        yv[lane*3 + 2] = vn2;
        __syncwarp();
        float a = 0.f, u0 = 0.f, u1 = 0.f, u2 = 0.f;
#pragma unroll
        for (int k = 0; k < CC; k++) {
            float ws = sWus[k*CC + lane], wv = sWuv[k*CC + lane];
            a  += ys[k]     * ws;
            u0 += yv[k*3+0] * wv;
            u1 += yv[k*3+1] * wv;
            u2 += yv[k*3+2] * wv;
        }
        g_up [n*CC + lane] = make_float4(a, u0, u1, u2);
        g_acc[n*CC + lane] = make_float4(0.f, 0.f, 0.f, 0.f);
    }
}

// ---------------- launch ------------------------------------------------------
extern "C" void kernel_launch(void* const* d_in, const int* in_sizes, int n_in,
                              void* d_out, int out_size) {
    const float* pos     = (const float*)d_in[0];
    const float* attrs   = (const float*)d_in[1];
    const float* shifts  = (const float*)d_in[2];
    const float* W_embed = (const float*)d_in[3];
    const float* W_up_s  = (const float*)d_in[4];
    const float* W_up_v  = (const float*)d_in[5];
    const float* R1      = (const float*)d_in[6];
    const float* R2      = (const float*)d_in[7];
    const float* R3      = (const float*)d_in[8];
    const float* W_out_s = (const float*)d_in[9];
    const float* W_out_v = (const float*)d_in[10];
    const float* Wsc_s   = (const float*)d_in[11];
    const float* Wsc_v   = (const float*)d_in[12];
    const float* Wp      = (const float*)d_in[13];
    const float* W_lin_s = (const float*)d_in[14];
    const float* W_lin_v = (const float*)d_in[15];
    const int*   ei      = (const int*)d_in[16];
    const int* src = ei;
    const int* dst = ei + EE;
    float* out = (float*)d_out;

    int smemT = (NB*HH + HH*HH + HH*5*CC) * (int)sizeof(float);   // 59392 B
    cudaFuncSetAttribute(k_table, cudaFuncAttributeMaxDynamicSharedMemorySize, smemT);

    k_zidx <<<(NN + 255)/256, 256>>>(attrs);
    k_pre0 <<<1, ZZ*32>>>(W_embed, W_up_s);
    k_init0<<<(NN*CC + 255)/256, 256>>>(W_embed);
    k_geom <<<(EE + 255)/256, 256>>>(pos, shifts, src, dst);
    k_table<<<TT/8, 256, smemT>>>(R1, R2, R3, 0);
    k_table<<<TT/8, 256, smemT>>>(R1 + NB*HH, R2 + HH*HH, R3 + HH*5*CC, 1);

    const int EGRID = 148*8;   // 256 thr/blk, grid-stride over edges

    // layer 0 (v == 0 → 2-path, ss from species table)
    k_edge2<2><<<EGRID, 256>>>(0);
    k_nodeupd<true><<<(NN + NWB - 1)/NWB, NWB*32>>>(
        W_out_s, W_out_v, Wsc_s, Wsc_v, Wp, W_lin_s, W_lin_v,
        W_up_s + CC*CC, W_up_v + CC*CC, out, 0);

    // layer 1 (full 5-path)
    k_edge2<5><<<EGRID, 256>>>(1);
    k_nodeupd<false><<<(NN + NWB - 1)/NWB, NWB*32>>>(
        W_out_s + CC*CC, W_out_v + CC*CC,
        Wsc_s + ZZ*CC*CC, Wsc_v + ZZ*CC*CC, Wp + ZZ*5*CC,
        W_lin_s + CC*CC, W_lin_v + CC*CC,
        W_up_s, W_up_v, out, 1);
}

// round 14
// speedup vs baseline: 4.8708x; 1.2896x over previous
#include <cuda_runtime.h>
#include <math.h>

#define NN 50000
#define EE 800000
#define CC 32
#define ZZ 10
#define LL 2
#define NB 8
#define HH 64
#define TT 8192
#define INV_AVG (1.0f/16.0f)
#define RCUT_INV (1.0f/5.0f)

// ---------------- scratch (static device globals; no allocation) -------------
__device__ float4 g_sv [NN*CC];   // {s, v0, v1, v2}
__device__ float4 g_up [NN*CC];   // {su, vu0, vu1, vu2}
__device__ float4 g_acc[NN*CC];   // {S, V0, V1, V2}
__device__ float4 g_Y1 [EE];      // unsorted edge geometry
__device__ float  g_tc [EE];      // table coordinate (r mapped to [0, TT-1])
__device__ int2   g_edge [EE];    // {src, dst}
__device__ int2   g_edge0[EE];    // {z[src], dst}
__device__ int    g_z  [NN];
__device__ float  g_su0[ZZ*CC];   // layer-0 su table (species-only)
__device__ float  g_wtab[LL*TT*5*CC];  // radial-MLP output table per layer
// sorted/compacted active-edge arrays (counting sort by table bin)
__device__ int    g_bcnt[TT];
__device__ int    g_pos [TT];
__device__ int    g_M;            // number of active edges (r < rcut)
__device__ float4 g_Y1s [EE];
__device__ float  g_tcs [EE];
__device__ int2   g_edges [EE];
__device__ int2   g_edge0s[EE];

__device__ __forceinline__ float silu(float x) {
    return __fdividef(x, 1.0f + __expf(-x));
}
__device__ __forceinline__ void red_v4(float4* p, float a, float b, float c, float d) {
    asm volatile("red.global.add.v4.f32 [%0], {%1,%2,%3,%4};"
                 :: "l"(p), "f"(a), "f"(b), "f"(c), "f"(d) : "memory");
}

// ---------------- species index from one-hot (+ zero histogram bins) ----------
__global__ void k_zidx(const float* __restrict__ attrs) {
    int n = blockIdx.x * blockDim.x + threadIdx.x;
    if (n >= NN) return;
    if (n < TT) g_bcnt[n] = 0;
    int z = 0;
#pragma unroll
    for (int j = 0; j < ZZ; j++)
        if (attrs[n*ZZ + j] > 0.5f) z = j;
    g_z[n] = z;
}

// ---------------- layer-0 su table: su0[z] = W_embed[z] @ W_up_s[0] ----------
__global__ void k_pre0(const float* __restrict__ W_embed,
                       const float* __restrict__ Wus) {
    int z = threadIdx.x >> 5, lane = threadIdx.x & 31;
    if (z >= ZZ) return;
    float a = 0.f;
#pragma unroll
    for (int k = 0; k < CC; k++)
        a += W_embed[z*CC + k] * Wus[k*CC + lane];
    g_su0[z*CC + lane] = a;
}

// ---------------- fused init: s=embed, v=0, up from table, acc=0 -------------
__global__ void k_init0(const float* __restrict__ W_embed) {
    int idx = blockIdx.x * blockDim.x + threadIdx.x;
    if (idx >= NN*CC) return;
    int n = idx >> 5, c = idx & 31;
    int z = g_z[n];
    g_sv [idx] = make_float4(W_embed[z*CC + c], 0.f, 0.f, 0.f);
    g_up [idx] = make_float4(g_su0[z*CC + c],   0.f, 0.f, 0.f);
    g_acc[idx] = make_float4(0.f, 0.f, 0.f, 0.f);
}

// ---------------- edge geometry: Y1 + table coord + histogram ----------------
// Edges with r >= rcut have fc=0 -> edge_feats=0 -> w=0 -> EXACT zero message
// (reference included); they are excluded from the histogram and never processed.
__global__ void k_geom(const float* __restrict__ pos,
                       const float* __restrict__ shifts,
                       const int* __restrict__ src,
                       const int* __restrict__ dst) {
    int e = blockIdx.x * blockDim.x + threadIdx.x;
    if (e >= EE) return;
    int si = src[e], di = dst[e];
    g_edge [e] = make_int2(si, di);
    g_edge0[e] = make_int2(__ldg(g_z + si), di);
    float vx = pos[di*3+0] - pos[si*3+0] + shifts[e*3+0];
    float vy = pos[di*3+1] - pos[si*3+1] + shifts[e*3+1];
    float vz = pos[di*3+2] - pos[si*3+2] + shifts[e*3+2];
    float r  = sqrtf(vx*vx + vy*vy + vz*vz);
    float rs = fmaxf(r, 1e-9f);
    float inv = 1.0f / rs;
    g_Y1[e] = make_float4(vx*inv, vy*inv, vz*inv, 0.f);
    float x = r * RCUT_INV;
    float tc = fminf(x, 1.0f) * (float)(TT - 1);
    g_tc[e] = tc;
    if (tc < (float)(TT - 1))
        atomicAdd(&g_bcnt[min((int)tc, TT - 2)], 1);
}

// ---------------- exclusive scan over 8192 bins (one block) ------------------
__global__ void k_scan() {
    __shared__ int s[1024];
    int t = threadIdx.x;
    int c[8], sum = 0;
#pragma unroll
    for (int j = 0; j < 8; j++) { c[j] = g_bcnt[t*8 + j]; sum += c[j]; }
    s[t] = sum;
    __syncthreads();
    for (int off = 1; off < 1024; off <<= 1) {
        int v = (t >= off) ? s[t - off] : 0;
        __syncthreads();
        s[t] += v;
        __syncthreads();
    }
    int run = (t == 0) ? 0 : s[t - 1];
#pragma unroll
    for (int j = 0; j < 8; j++) { g_pos[t*8 + j] = run; run += c[j]; }
    if (t == 1023) g_M = s[1023];
}

// ---------------- scatter active edges into bin-sorted order ------------------
__global__ void k_scatter() {
    int e = blockIdx.x * blockDim.x + threadIdx.x;
    if (e >= EE) return;
    float tc = g_tc[e];
    if (tc >= (float)(TT - 1)) return;        // zero-message edge: drop
    int bin = min((int)tc, TT - 2);
    int pos = atomicAdd(&g_pos[bin], 1);
    g_tcs   [pos] = tc;
    g_Y1s   [pos] = g_Y1[e];
    g_edges [pos] = g_edge[e];
    g_edge0s[pos] = g_edge0[e];
}

// ---------------- radial-MLP table build --------------------------------------
// Exact MLP (precise sinf basis, fp32) at TT uniform r-points; warp per entry.
__global__ void k_table(const float* __restrict__ R1,
                        const float* __restrict__ R2,
                        const float* __restrict__ R3, int layer) {
    extern __shared__ float sm[];
    float* sR1 = sm;                 // 8*64
    float* sR2 = sR1 + NB*HH;        // 64*64
    float* sR3 = sR2 + HH*HH;        // 64*160
    int tid = threadIdx.x;
    for (int i = tid; i < NB*HH;   i += blockDim.x) sR1[i] = R1[i];
    for (int i = tid; i < HH*HH;   i += blockDim.x) sR2[i] = R2[i];
    for (int i = tid; i < HH*5*CC; i += blockDim.x) sR3[i] = R3[i];
    __syncthreads();

    int warp = tid >> 5, lane = tid & 31;
    int i = blockIdx.x * (blockDim.x >> 5) + warp;
    if (i >= TT) return;

    float r  = 5.0f * (float)i / (float)(TT - 1);
    float rs = fmaxf(r, 1e-9f);
    float inv = 1.0f / rs;
    float x = r * RCUT_INV;
    float fc = 0.f;
    if (x < 1.0f) {
        float x2 = x*x, x3 = x2*x;
        float x6 = x3*x3, x7 = x6*x, x8 = x7*x;
        fc = 1.0f - 28.0f*x6 + 48.0f*x7 - 21.0f*x8;
    }
    float coef = 0.6324555320336759f * fc * inv;
    float arg0 = rs * (float)M_PI * RCUT_INV;
    float ef[NB];
#pragma unroll
    for (int nb = 0; nb < NB; nb++)
        ef[nb] = coef * sinf((float)(nb+1) * arg0);

    float h0 = 0.f, h1 = 0.f;
#pragma unroll
    for (int k = 0; k < NB; k++) {
        h0 += ef[k] * sR1[k*HH + lane];
        h1 += ef[k] * sR1[k*HH + lane + 32];
    }
    h0 = silu(h0); h1 = silu(h1);

    float a0 = 0.f, a1 = 0.f;
#pragma unroll
    for (int k = 0; k < 32; k++) {
        float va = __shfl_sync(0xffffffffu, h0, k);
        float vb = __shfl_sync(0xffffffffu, h1, k);
        a0 += va * sR2[k*HH + lane]        + vb * sR2[(k+32)*HH + lane];
        a1 += va * sR2[k*HH + lane + 32]   + vb * sR2[(k+32)*HH + lane + 32];
    }
    a0 = silu(a0); a1 = silu(a1);

    float w[5] = {0.f, 0.f, 0.f, 0.f, 0.f};
#pragma unroll
    for (int k = 0; k < 32; k++) {
        float va = __shfl_sync(0xffffffffu, a0, k);
        float vb = __shfl_sync(0xffffffffu, a1, k);
#pragma unroll
        for (int p = 0; p < 5; p++)
            w[p] += va * sR3[k*5*CC + p*CC + lane]
                  + vb * sR3[(k+32)*5*CC + p*CC + lane];
    }
    float* out = g_wtab + ((size_t)layer*TT + i) * (5*CC);
#pragma unroll
    for (int p = 0; p < 5; p++)
        out[p*CC + lane] = w[p];
}

// ---------------- edge kernel: sorted active edges, table interp + scatter ---
// Block owns a CONTIGUOUS chunk of bin-sorted edges -> neighboring edges share
// table rows -> table reads are L1 hits. Warp per edge; lane = channel.
#define EBLK 1184
template<int NP>
__global__ void __launch_bounds__(256)
k_edge2(int layer) {
    __shared__ float sSU0[ZZ*CC];
    if (NP == 2) {
        for (int i = threadIdx.x; i < ZZ*CC; i += blockDim.x) sSU0[i] = g_su0[i];
        __syncthreads();
    }
    int M = g_M;
    int chunk = (M + EBLK - 1) / EBLK;
    int start = blockIdx.x * chunk;
    int end   = min(start + chunk, M);
    int wib = threadIdx.x >> 5, lane = threadIdx.x & 31;
    const float* tab = g_wtab + (size_t)layer*TT*(5*CC);
    constexpr int NW = (NP == 2) ? 2 : 5;

    for (int e = start + wib; e < end; e += 8) {
        int2 sd = __ldg((NP == 2 ? g_edge0s : g_edges) + e);
        float tc = __ldg(g_tcs + e);
        int i0 = min((int)tc, TT - 2);
        float f = tc - (float)i0;
        const float* rowA = tab + (size_t)i0 * (5*CC);
        float w[NW];
#pragma unroll
        for (int p = 0; p < NW; p++) {
            float a = __ldg(rowA + p*CC + lane);
            float b = __ldg(rowA + 5*CC + p*CC + lane);
            w[p] = fmaf(f, b - a, a);
        }
        float4 y4 = __ldg(g_Y1s + e);
        float y0 = y4.x, y1 = y4.y, y2 = y4.z;
        float ms, m0, m1, m2;
        if (NP == 2) {
            float ss = sSU0[sd.x*CC + lane];
            ms = w[0] * ss;
            float w1s = w[1] * ss;
            m0 = w1s*y0; m1 = w1s*y1; m2 = w1s*y2;
        } else {
            float4 uv = __ldg(g_up + sd.x*CC + lane);
            float ss = uv.x, v0 = uv.y, v1 = uv.z, v2 = uv.w;
            float dot = v0*y0 + v1*y1 + v2*y2;
            float c0 = v1*y2 - v2*y1;
            float c1 = v2*y0 - v0*y2;
            float c2 = v0*y1 - v1*y0;
            ms = w[0]*ss + w[3]*dot;
            m0 = w[1]*ss*y0 + w[2]*v0 + w[4]*c0;
            m1 = w[1]*ss*y1 + w[2]*v1 + w[4]*c1;
            m2 = w[1]*ss*y2 + w[2]*v2 + w[4]*c2;
        }
        red_v4(g_acc + sd.y*CC + lane, ms, m0, m1, m2);
    }
}

// ---------------- node update: out linears, skip, product block --------------
#define NWB 16
template<bool FUSE>
__global__ void k_nodeupd(const float* __restrict__ Wouts,
                          const float* __restrict__ Woutv,
                          const float* __restrict__ Wscs,
                          const float* __restrict__ Wscv,
                          const float* __restrict__ Wp,
                          const float* __restrict__ Wlins,
                          const float* __restrict__ Wlinv,
                          const float* __restrict__ WusN,
                          const float* __restrict__ WuvN,
                          float* __restrict__ out, int l) {
    __shared__ float sWos[CC*CC], sWov[CC*CC], sWls[CC*CC], sWlv[CC*CC];
    __shared__ float sWus[CC*CC], sWuv[CC*CC];
    __shared__ float st[NWB][256];
    int tid = threadIdx.x;
    for (int i = tid; i < CC*CC; i += blockDim.x) {
        sWos[i] = Wouts[i]; sWov[i] = Woutv[i];
        sWls[i] = Wlins[i]; sWlv[i] = Wlinv[i];
        if (FUSE) { sWus[i] = WusN[i]; sWuv[i] = WuvN[i]; }
    }
    __syncthreads();
    int warp = tid >> 5, lane = tid & 31;
    int n = blockIdx.x * NWB + warp;
    if (n >= NN) return;

    float* xs = st[warp];
    float* xv = xs + 32;
    float* ys = xv + 96;
    float* yv = ys + 32;

    int z = g_z[n];
    float4 a4 = g_acc[n*CC + lane];
    float4 o4 = g_sv [n*CC + lane];
    xs[lane]       = a4.x * INV_AVG;
    xv[lane*3 + 0] = a4.y * INV_AVG;
    xv[lane*3 + 1] = a4.z * INV_AVG;
    xv[lane*3 + 2] = a4.w * INV_AVG;
    ys[lane]       = o4.x;
    yv[lane*3 + 0] = o4.y;
    yv[lane*3 + 1] = o4.z;
    yv[lane*3 + 2] = o4.w;
    __syncwarp();

    const float* Ws = Wscs + z*CC*CC;
    const float* Wv = Wscv + z*CC*CC;
    float s2 = 0.f, v20 = 0.f, v21 = 0.f, v22 = 0.f;
    float scs = 0.f, sv0 = 0.f, sv1 = 0.f, sv2 = 0.f;
#pragma unroll
    for (int k = 0; k < CC; k++) {
        float wo = sWos[k*CC + lane], wvv = sWov[k*CC + lane];
        s2  += xs[k]     * wo;
        v20 += xv[k*3+0] * wvv;
        v21 += xv[k*3+1] * wvv;
        v22 += xv[k*3+2] * wvv;
        float as = __ldg(Ws + k*CC + lane), av = __ldg(Wv + k*CC + lane);
        scs += ys[k]     * as;
        sv0 += yv[k*3+0] * av;
        sv1 += yv[k*3+1] * av;
        sv2 += yv[k*3+2] * av;
    }

    float we0 = __ldg(Wp + (z*5+0)*CC + lane);
    float we1 = __ldg(Wp + (z*5+1)*CC + lane);
    float we2 = __ldg(Wp + (z*5+2)*CC + lane);
    float we3 = __ldg(Wp + (z*5+3)*CC + lane);
    float we4 = __ldg(Wp + (z*5+4)*CC + lane);

    float vdot = v20*v20 + v21*v21 + v22*v22;
    float ps  = we0*s2 + we1*s2*s2 + we2*vdot;
    float pv0 = we3*v20 + we4*s2*v20;
    float pv1 = we3*v21 + we4*s2*v21;
    float pv2 = we3*v22 + we4*s2*v22;
    __syncwarp();
    xs[lane] = ps;
    xv[lane*3+0] = pv0; xv[lane*3+1] = pv1; xv[lane*3+2] = pv2;
    __syncwarp();

    float sn = scs, vn0 = sv0, vn1 = sv1, vn2 = sv2;
#pragma unroll
    for (int k = 0; k < CC; k++) {
        float wl = sWls[k*CC + lane], wlv = sWlv[k*CC + lane];
        sn  += xs[k]     * wl;
        vn0 += xv[k*3+0] * wlv;
        vn1 += xv[k*3+1] * wlv;
        vn2 += xv[k*3+2] * wlv;
    }
    g_sv[n*CC + lane] = make_float4(sn, vn0, vn1, vn2);
    out[n*(LL*CC) + l*CC + lane] = sn;

    if (FUSE) {
        __syncwarp();
        ys[lane]       = sn;
        yv[lane*3 + 0] = vn0;
        yv[lane*3 + 1] = vn1;
        yv[lane*3 + 2] = vn2;
        __syncwarp();
        float a = 0.f, u0 = 0.f, u1 = 0.f, u2 = 0.f;
#pragma unroll
        for (int k = 0; k < CC; k++) {
            float ws = sWus[k*CC + lane], wv = sWuv[k*CC + lane];
            a  += ys[k]     * ws;
            u0 += yv[k*3+0] * wv;
            u1 += yv[k*3+1] * wv;
            u2 += yv[k*3+2] * wv;
        }
        g_up [n*CC + lane] = make_float4(a, u0, u1, u2);
        g_acc[n*CC + lane] = make_float4(0.f, 0.f, 0.f, 0.f);
    }
}

// ---------------- launch ------------------------------------------------------
extern "C" void kernel_launch(void* const* d_in, const int* in_sizes, int n_in,
                              void* d_out, int out_size) {
    const float* pos     = (const float*)d_in[0];
    const float* attrs   = (const float*)d_in[1];
    const float* shifts  = (const float*)d_in[2];
    const float* W_embed = (const float*)d_in[3];
    const float* W_up_s  = (const float*)d_in[4];
    const float* W_up_v  = (const float*)d_in[5];
    const float* R1      = (const float*)d_in[6];
    const float* R2      = (const float*)d_in[7];
    const float* R3      = (const float*)d_in[8];
    const float* W_out_s = (const float*)d_in[9];
    const float* W_out_v = (const float*)d_in[10];
    const float* Wsc_s   = (const float*)d_in[11];
    const float* Wsc_v   = (const float*)d_in[12];
    const float* Wp      = (const float*)d_in[13];
    const float* W_lin_s = (const float*)d_in[14];
    const float* W_lin_v = (const float*)d_in[15];
    const int*   ei      = (const int*)d_in[16];
    const int* src = ei;
    const int* dst = ei + EE;
    float* out = (float*)d_out;

    int smemT = (NB*HH + HH*HH + HH*5*CC) * (int)sizeof(float);   // 59392 B
    cudaFuncSetAttribute(k_table, cudaFuncAttributeMaxDynamicSharedMemorySize, smemT);

    k_zidx <<<(NN + 255)/256, 256>>>(attrs);
    k_pre0 <<<1, ZZ*32>>>(W_embed, W_up_s);
    k_init0<<<(NN*CC + 255)/256, 256>>>(W_embed);
    k_geom <<<(EE + 255)/256, 256>>>(pos, shifts, src, dst);
    k_scan <<<1, 1024>>>();
    k_scatter<<<(EE + 255)/256, 256>>>();
    k_table<<<TT/8, 256, smemT>>>(R1, R2, R3, 0);
    k_table<<<TT/8, 256, smemT>>>(R1 + NB*HH, R2 + HH*HH, R3 + HH*5*CC, 1);

    // layer 0 (v == 0 → 2-path, ss from species table)
    k_edge2<2><<<EBLK, 256>>>(0);
    k_nodeupd<true><<<(NN + NWB - 1)/NWB, NWB*32>>>(
        W_out_s, W_out_v, Wsc_s, Wsc_v, Wp, W_lin_s, W_lin_v,
        W_up_s + CC*CC, W_up_v + CC*CC, out, 0);

    // layer 1 (full 5-path)
    k_edge2<5><<<EBLK, 256>>>(1);
    k_nodeupd<false><<<(NN + NWB - 1)/NWB, NWB*32>>>(
        W_out_s + CC*CC, W_out_v + CC*CC,
        Wsc_s + ZZ*CC*CC, Wsc_v + ZZ*CC*CC, Wp + ZZ*5*CC,
        W_lin_s + CC*CC, W_lin_v + CC*CC,
        W_up_s, W_up_v, out, 1);
}